// round 7
// baseline (speedup 1.0000x reference)
#include <cuda_runtime.h>
#include <cuda_fp16.h>
#include <math.h>
#include <stdint.h>

// Problem constants: B=16, C=512, H=W=32, GROUPS=32
#define BB   16
#define CC   512
#define NN_  1024
#define CG   16
#define SCALE 0.044194173824159216f   // 512^-0.5

// ---------------------------------------------------------------------------
// Scratch (device globals)
// ---------------------------------------------------------------------------
__device__ __align__(128) __half g_xn [(size_t)BB * NN_ * CC];   // xn_t [b][n][c]
__device__ __align__(128) __half g_wq [(size_t)3 * CC * CC];     // w_qkv fp16
__device__ __align__(128) __half g_wp [(size_t)CC * CC];         // w_proj fp16
__device__ __align__(128) __half g_qkt[(size_t)BB * NN_ * NN_];  // [b][n][o] (q|k)
__device__ __align__(128) __half g_v  [(size_t)BB * CC * NN_];   // v [b][c][n]
__device__ __align__(128) __half g_s  [(size_t)BB * NN_ * NN_];  // scaled scores fp16
__device__ __align__(128) __half g_av [(size_t)BB * NN_ * CC];   // av_t [b][n][c]

// ---------------------------------------------------------------------------
// Helpers (base-target sm_80+ only)
// ---------------------------------------------------------------------------
__device__ __forceinline__ uint32_t smem_u32(const void* p) {
    uint32_t a;
    asm("{ .reg .u64 t; cvta.to.shared.u64 t, %1; cvt.u32.u64 %0, t; }" : "=r"(a) : "l"(p));
    return a;
}
__device__ __forceinline__ void ldsm4(uint32_t (&r)[4], uint32_t addr) {
    asm volatile("ldmatrix.sync.aligned.m8n8.x4.shared.b16 {%0,%1,%2,%3}, [%4];"
        : "=r"(r[0]), "=r"(r[1]), "=r"(r[2]), "=r"(r[3]) : "r"(addr));
}
__device__ __forceinline__ void ldsm2(uint32_t (&r)[2], uint32_t addr) {
    asm volatile("ldmatrix.sync.aligned.m8n8.x2.shared.b16 {%0,%1}, [%2];"
        : "=r"(r[0]), "=r"(r[1]) : "r"(addr));
}
__device__ __forceinline__ void mma16816(float (&c)[4], const uint32_t (&a)[4],
                                         const uint32_t (&b)[2]) {
    asm volatile("mma.sync.aligned.m16n8k16.row.col.f32.f16.f16.f32 "
        "{%0,%1,%2,%3}, {%4,%5,%6,%7}, {%8,%9}, {%0,%1,%2,%3};"
        : "+f"(c[0]), "+f"(c[1]), "+f"(c[2]), "+f"(c[3])
        : "r"(a[0]), "r"(a[1]), "r"(a[2]), "r"(a[3]), "r"(b[0]), "r"(b[1]));
}
__device__ __forceinline__ void cp16(uint32_t dst, const void* src) {
    asm volatile("cp.async.cg.shared.global [%0], [%1], 16;" :: "r"(dst), "l"(src));
}
__device__ __forceinline__ void cp_commit() {
    asm volatile("cp.async.commit_group;" ::: "memory");
}
template<int N> __device__ __forceinline__ void cp_wait() {
    asm volatile("cp.async.wait_group %0;" :: "n"(N) : "memory");
}

// ---------------------------------------------------------------------------
// fp32 -> fp16 convert
// ---------------------------------------------------------------------------
__global__ void cvt_kernel(const float* __restrict__ src, __half* __restrict__ dst, int n) {
    int i = blockIdx.x * blockDim.x + threadIdx.x;
    if (i < n) dst[i] = __float2half_rn(src[i]);
}

// ---------------------------------------------------------------------------
// GroupNorm -> transposed fp16 output xn_t[b][n][c]
// ---------------------------------------------------------------------------
__global__ void gn_kernel(const float* __restrict__ x,
                          const float* __restrict__ gamma,
                          const float* __restrict__ beta) {
    extern __shared__ float xs[];              // 16 ch x 1024 px
    const int b = blockIdx.x >> 5;
    const int g = blockIdx.x & 31;
    const size_t base = ((size_t)b * CC + (size_t)g * CG) * NN_;
    const float4* __restrict__ x4 = (const float4*)(x + base);

    float s = 0.f, s2 = 0.f;
    for (int i = threadIdx.x; i < CG * NN_ / 4; i += 256) {
        float4 v = x4[i];
        ((float4*)xs)[i] = v;
        s  += v.x + v.y + v.z + v.w;
        s2 += v.x * v.x + v.y * v.y + v.z * v.z + v.w * v.w;
    }
    #pragma unroll
    for (int o = 16; o; o >>= 1) {
        s  += __shfl_down_sync(0xffffffffu, s,  o);
        s2 += __shfl_down_sync(0xffffffffu, s2, o);
    }
    __shared__ float2 sh[8];
    __shared__ float sga[16], sbe[16];
    if ((threadIdx.x & 31) == 0) sh[threadIdx.x >> 5] = make_float2(s, s2);
    __syncthreads();
    if (threadIdx.x < 16) {
        float ts = 0.f, ts2 = 0.f;
        #pragma unroll
        for (int i = 0; i < 8; i++) { ts += sh[i].x; ts2 += sh[i].y; }
        const float inv = 1.f / (float)(CG * NN_);
        float mu  = ts * inv;
        float var = ts2 * inv - mu * mu;
        float rstd = rsqrtf(var + 1e-5f);
        int c = g * CG + threadIdx.x;
        float ga = gamma[c] * rstd;
        sga[threadIdx.x] = ga;
        sbe[threadIdx.x] = beta[c] - mu * ga;
    }
    __syncthreads();

    for (int n = threadIdx.x; n < NN_; n += 256) {
        __align__(16) __half hh[16];
        #pragma unroll
        for (int c = 0; c < 16; c++)
            hh[c] = __float2half_rn(xs[c * NN_ + n] * sga[c] + sbe[c]);
        size_t o = ((size_t)(b * NN_ + n)) * CC + g * CG;
        *(uint4*)(g_xn + o)     = *(uint4*)(hh);
        *(uint4*)(g_xn + o + 8) = *(uint4*)(hh + 8);
    }
}

// ---------------------------------------------------------------------------
// fp16 HMMA GEMM:  D[M,N] = sum_k A[m][k] * B[n][k]   (both K-major)
// 128x128 CTA tile, BK=64, 8 warps (64x32), 3-stage cp.async ring, 2 CTA/SM.
// EPI: 0=fp16+col bias, 1=fp16+row bias, 2=fp16*SCALE, 4=fp32+row bias+resid
// ---------------------------------------------------------------------------
#define STAGE_BYTES 32768              // A 16KB + B 16KB
#define NSTAGE      3
#define SMEM_BYTES  (NSTAGE * STAGE_BYTES)

template<int EPI>
__global__ void __launch_bounds__(256, 2) gemm_hh(
    const __half* __restrict__ A, size_t aBatch, int ldA,
    const __half* __restrict__ B, size_t bBatch, int ldB,
    int K,
    __half* __restrict__ outH, float* __restrict__ outF,
    size_t oBatch, int ldO,
    const float* __restrict__ bias, const float* __restrict__ resid)
{
    extern __shared__ char smem[];
    const uint32_t sb = smem_u32(smem);

    const int tid = threadIdx.x, lane = tid & 31, wid = tid >> 5;
    const int wm = wid >> 2, wn = wid & 3;
    const int b  = blockIdx.z;
    const int m0 = blockIdx.y * 128, n0 = blockIdx.x * 128;

    const __half* srcA = A + (size_t)b * aBatch + (size_t)m0 * ldA;
    const __half* srcB = B + (size_t)b * bBatch + (size_t)n0 * ldB;

    float acc[4][4][4];
    #pragma unroll
    for (int i = 0; i < 4; i++)
        #pragma unroll
        for (int j = 0; j < 4; j++)
            #pragma unroll
            for (int q = 0; q < 4; q++) acc[i][j][q] = 0.f;

    const int T = K / 64;

    const int l_row = tid >> 1;
    const int l_g0  = (tid & 1) * 4;
    auto load_stage = [&](int t) {
        const int k0 = t * 64;
        const uint32_t sbuf = sb + (uint32_t)(t % NSTAGE) * STAGE_BYTES;
        const uint32_t rowOff = (uint32_t)l_row * 128;
        #pragma unroll
        for (int q = 0; q < 4; q++) {
            const int g = l_g0 + q;
            const uint32_t sw = (uint32_t)((g ^ (l_row & 7)) << 4);
            cp16(sbuf + rowOff + sw,          srcA + (size_t)l_row * ldA + k0 + g * 8);
            cp16(sbuf + 16384 + rowOff + sw,  srcB + (size_t)l_row * ldB + k0 + g * 8);
        }
    };

    const int arow = lane & 15;
    const int akhi = lane >> 4;
    const int brow = lane & 7;
    const int bkhi = (lane >> 3) & 1;
    const uint32_t aRowOff = (uint32_t)(wm * 64 + arow) * 128;
    const uint32_t bRowOff = (uint32_t)(wn * 32 + brow) * 128 + 16384u;

    load_stage(0); cp_commit();
    load_stage(1); cp_commit();

    for (int t = 0; t < T; t++) {
        cp_wait<1>();
        __syncthreads();
        if (t + 2 < T) load_stage(t + 2);
        cp_commit();

        const uint32_t sbuf = sb + (uint32_t)(t % NSTAGE) * STAGE_BYTES;
        #pragma unroll
        for (int k16 = 0; k16 < 4; k16++) {
            const uint32_t aSw = (uint32_t)(((k16 * 2 + akhi) ^ (arow & 7)) << 4);
            const uint32_t bSw = (uint32_t)(((k16 * 2 + bkhi) ^ brow) << 4);
            uint32_t af[4][4], bf[4][2];
            #pragma unroll
            for (int i = 0; i < 4; i++)
                ldsm4(af[i], sbuf + aRowOff + (uint32_t)(i * 16 * 128) + aSw);
            #pragma unroll
            for (int j = 0; j < 4; j++)
                ldsm2(bf[j], sbuf + bRowOff + (uint32_t)(j * 8 * 128) + bSw);
            #pragma unroll
            for (int i = 0; i < 4; i++)
                #pragma unroll
                for (int j = 0; j < 4; j++)
                    mma16816(acc[i][j], af[i], bf[j]);
        }
    }

    // epilogue
    const int rbase = m0 + wm * 64 + (lane >> 2);
    const int cbase = n0 + wn * 32 + (lane & 3) * 2;

    float bc0[4], bc1[4];
    if (EPI == 0) {
        #pragma unroll
        for (int j = 0; j < 4; j++) { bc0[j] = bias[cbase + j * 8]; bc1[j] = bias[cbase + j * 8 + 1]; }
    }

    #pragma unroll
    for (int i = 0; i < 4; i++) {
        const int row0 = rbase + i * 16, row1 = row0 + 8;
        float br0 = 0.f, br1 = 0.f;
        if (EPI == 1 || EPI == 4) { br0 = bias[row0]; br1 = bias[row1]; }
        #pragma unroll
        for (int j = 0; j < 4; j++) {
            const int col = cbase + j * 8;
            const size_t ob0 = (size_t)b * oBatch + (size_t)row0 * ldO + col;
            const size_t ob1 = (size_t)b * oBatch + (size_t)row1 * ldO + col;
            float v0 = acc[i][j][0], v1 = acc[i][j][1];
            float v2 = acc[i][j][2], v3 = acc[i][j][3];
            if (EPI == 2) {
                *(__half2*)(outH + ob0) = __floats2half2_rn(v0 * SCALE, v1 * SCALE);
                *(__half2*)(outH + ob1) = __floats2half2_rn(v2 * SCALE, v3 * SCALE);
            } else if (EPI == 4) {
                float2 r0 = *(const float2*)(resid + ob0);
                float2 r1 = *(const float2*)(resid + ob1);
                *(float2*)(outF + ob0) = make_float2(v0 + br0 + r0.x, v1 + br0 + r0.y);
                *(float2*)(outF + ob1) = make_float2(v2 + br1 + r1.x, v3 + br1 + r1.y);
            } else {
                if (EPI == 0) { v0 += bc0[j]; v1 += bc1[j]; v2 += bc0[j]; v3 += bc1[j]; }
                if (EPI == 1) { v0 += br0;    v1 += br0;    v2 += br1;    v3 += br1;   }
                *(__half2*)(outH + ob0) = __floats2half2_rn(v0, v1);
                *(__half2*)(outH + ob1) = __floats2half2_rn(v2, v3);
            }
        }
    }
}

// ---------------------------------------------------------------------------
// Fused online-softmax + AV GEMM (flash style).
// A = scaled scores S[b][i][j] fp16 (exp applied in-place per tile),
// B = V[b][c][j] fp16.  D[i][c] = softmax_j(S[i][:]) . V[c][:]
// Same tiling as gemm_hh; running row max m / sum l in shared; acc rescaled.
// ---------------------------------------------------------------------------
__global__ void __launch_bounds__(256, 2) av_fused(
    const __half* __restrict__ S, const __half* __restrict__ V,
    __half* __restrict__ O)
{
    extern __shared__ char smem[];
    const uint32_t sb = smem_u32(smem);
    __shared__ float sm_m[128], sm_l[128], sm_f[128];

    const int tid = threadIdx.x, lane = tid & 31, wid = tid >> 5;
    const int wm = wid >> 2, wn = wid & 3;
    const int b  = blockIdx.z;
    const int m0 = blockIdx.y * 128, n0 = blockIdx.x * 128;

    const __half* srcA = S + (size_t)b * NN_ * NN_ + (size_t)m0 * NN_;
    const __half* srcB = V + (size_t)b * CC  * NN_ + (size_t)n0 * NN_;

    float acc[4][4][4];
    #pragma unroll
    for (int i = 0; i < 4; i++)
        #pragma unroll
        for (int j = 0; j < 4; j++)
            #pragma unroll
            for (int q = 0; q < 4; q++) acc[i][j][q] = 0.f;

    if (tid < 128) { sm_m[tid] = -1e30f; sm_l[tid] = 0.f; }

    const int T = NN_ / 64;    // 16

    const int l_row = tid >> 1;
    const int l_g0  = (tid & 1) * 4;
    auto load_stage = [&](int t) {
        const int k0 = t * 64;
        const uint32_t sbuf = sb + (uint32_t)(t % NSTAGE) * STAGE_BYTES;
        const uint32_t rowOff = (uint32_t)l_row * 128;
        #pragma unroll
        for (int q = 0; q < 4; q++) {
            const int g = l_g0 + q;
            const uint32_t sw = (uint32_t)((g ^ (l_row & 7)) << 4);
            cp16(sbuf + rowOff + sw,          srcA + (size_t)l_row * NN_ + k0 + g * 8);
            cp16(sbuf + 16384 + rowOff + sw,  srcB + (size_t)l_row * NN_ + k0 + g * 8);
        }
    };

    const int arow = lane & 15;
    const int akhi = lane >> 4;
    const int brow = lane & 7;
    const int bkhi = (lane >> 3) & 1;
    const uint32_t aRowOff = (uint32_t)(wm * 64 + arow) * 128;
    const uint32_t bRowOff = (uint32_t)(wn * 32 + brow) * 128 + 16384u;

    // S-transform indexing: thread pair (2r, 2r+1) owns row r; 4x16B chunks each.
    const int pr = tid >> 1;
    const int ph = tid & 1;
    const uint32_t prOff = (uint32_t)pr * 128;

    // acc row indices for rescale
    const int accr = (lane >> 2);

    load_stage(0); cp_commit();
    load_stage(1); cp_commit();

    for (int t = 0; t < T; t++) {
        cp_wait<1>();
        __syncthreads();                 // stage t visible; init visible (t==0)
        if (t + 2 < T) load_stage(t + 2);
        cp_commit();

        const uint32_t sbuf = sb + (uint32_t)(t % NSTAGE) * STAGE_BYTES;

        // ---- in-place online softmax transform on S tile ----
        uint32_t raw[16];
        #pragma unroll
        for (int q = 0; q < 4; q++) {
            const int g = ph * 4 + q;
            const uint32_t a = sbuf + prOff + (uint32_t)((g ^ (pr & 7)) << 4);
            uint4 vv = *(uint4*)(uintptr_t)0;   // placeholder avoided below
            asm volatile("ld.shared.v4.u32 {%0,%1,%2,%3}, [%4];"
                : "=r"(raw[q*4+0]), "=r"(raw[q*4+1]), "=r"(raw[q*4+2]), "=r"(raw[q*4+3])
                : "r"(a));
            (void)vv;
        }
        float mx = -1e30f;
        #pragma unroll
        for (int q = 0; q < 16; q++) {
            float2 xf = __half22float2(*(const __half2*)&raw[q]);
            mx = fmaxf(mx, fmaxf(xf.x, xf.y));
        }
        mx = fmaxf(mx, __shfl_xor_sync(0xffffffffu, mx, 1));
        const float m_old = sm_m[pr];
        const float m_new = fmaxf(m_old, mx);
        const float f = __expf(m_old - m_new);
        float sum = 0.f;
        #pragma unroll
        for (int q = 0; q < 16; q++) {
            float2 xf = __half22float2(*(const __half2*)&raw[q]);
            float e0 = __expf(xf.x - m_new);
            float e1 = __expf(xf.y - m_new);
            sum += e0 + e1;
            __half2 h = __floats2half2_rn(e0, e1);
            raw[q] = *(const uint32_t*)&h;
        }
        #pragma unroll
        for (int q = 0; q < 4; q++) {
            const int g = ph * 4 + q;
            const uint32_t a = sbuf + prOff + (uint32_t)((g ^ (pr & 7)) << 4);
            asm volatile("st.shared.v4.u32 [%0], {%1,%2,%3,%4};"
                :: "r"(a), "r"(raw[q*4+0]), "r"(raw[q*4+1]), "r"(raw[q*4+2]), "r"(raw[q*4+3]));
        }
        sum += __shfl_xor_sync(0xffffffffu, sum, 1);
        if (ph == 0) {
            sm_m[pr] = m_new;
            sm_l[pr] = sm_l[pr] * f + sum;
            sm_f[pr] = f;
        }
        __syncthreads();                 // exp values + f visible to all warps

        // ---- rescale accumulators ----
        #pragma unroll
        for (int i = 0; i < 4; i++) {
            const float f0 = sm_f[wm * 64 + i * 16 + accr];
            const float f1 = sm_f[wm * 64 + i * 16 + 8 + accr];
            #pragma unroll
            for (int j = 0; j < 4; j++) {
                acc[i][j][0] *= f0; acc[i][j][1] *= f0;
                acc[i][j][2] *= f1; acc[i][j][3] *= f1;
            }
        }

        // ---- mma ----
        #pragma unroll
        for (int k16 = 0; k16 < 4; k16++) {
            const uint32_t aSw = (uint32_t)(((k16 * 2 + akhi) ^ (arow & 7)) << 4);
            const uint32_t bSw = (uint32_t)(((k16 * 2 + bkhi) ^ brow) << 4);
            uint32_t af[4][4], bf[4][2];
            #pragma unroll
            for (int i = 0; i < 4; i++)
                ldsm4(af[i], sbuf + aRowOff + (uint32_t)(i * 16 * 128) + aSw);
            #pragma unroll
            for (int j = 0; j < 4; j++)
                ldsm2(bf[j], sbuf + bRowOff + (uint32_t)(j * 8 * 128) + bSw);
            #pragma unroll
            for (int i = 0; i < 4; i++)
                #pragma unroll
                for (int j = 0; j < 4; j++)
                    mma16816(acc[i][j], af[i], bf[j]);
        }
    }

    // epilogue: divide by l, write av_t[b][i][c] fp16
    const int rbase = m0 + wm * 64 + (lane >> 2);
    const int cbase = n0 + wn * 32 + (lane & 3) * 2;
    #pragma unroll
    for (int i = 0; i < 4; i++) {
        const int row0 = rbase + i * 16, row1 = row0 + 8;
        const float rl0 = 1.f / sm_l[wm * 64 + i * 16 + accr];
        const float rl1 = 1.f / sm_l[wm * 64 + i * 16 + 8 + accr];
        #pragma unroll
        for (int j = 0; j < 4; j++) {
            const int col = cbase + j * 8;
            const size_t ob0 = (size_t)b * NN_ * CC + (size_t)row0 * CC + col;
            const size_t ob1 = (size_t)b * NN_ * CC + (size_t)row1 * CC + col;
            *(__half2*)(g_av + ob0) = __floats2half2_rn(acc[i][j][0] * rl0, acc[i][j][1] * rl0);
            *(__half2*)(g_av + ob1) = __floats2half2_rn(acc[i][j][2] * rl1, acc[i][j][3] * rl1);
        }
    }
}

// ---------------------------------------------------------------------------
// Launch
// ---------------------------------------------------------------------------
extern "C" void kernel_launch(void* const* d_in, const int* in_sizes, int n_in,
                              void* d_out, int out_size) {
    const float* x      = (const float*)d_in[0];
    const float* gamma  = (const float*)d_in[1];
    const float* beta   = (const float*)d_in[2];
    const float* w_qkv  = (const float*)d_in[3];
    const float* b_qkv  = (const float*)d_in[4];
    const float* w_proj = (const float*)d_in[5];
    const float* b_proj = (const float*)d_in[6];
    float* y = (float*)d_out;

    cudaFuncSetAttribute(gn_kernel,  cudaFuncAttributeMaxDynamicSharedMemorySize, 65536);
    cudaFuncSetAttribute(gemm_hh<0>, cudaFuncAttributeMaxDynamicSharedMemorySize, SMEM_BYTES);
    cudaFuncSetAttribute(gemm_hh<1>, cudaFuncAttributeMaxDynamicSharedMemorySize, SMEM_BYTES);
    cudaFuncSetAttribute(gemm_hh<2>, cudaFuncAttributeMaxDynamicSharedMemorySize, SMEM_BYTES);
    cudaFuncSetAttribute(gemm_hh<4>, cudaFuncAttributeMaxDynamicSharedMemorySize, SMEM_BYTES);
    cudaFuncSetAttribute(av_fused,   cudaFuncAttributeMaxDynamicSharedMemorySize, SMEM_BYTES);

    __half *xn, *wq, *wp, *qkt, *v, *s16, *av;
    cudaGetSymbolAddress((void**)&xn,  g_xn);
    cudaGetSymbolAddress((void**)&wq,  g_wq);
    cudaGetSymbolAddress((void**)&wp,  g_wp);
    cudaGetSymbolAddress((void**)&qkt, g_qkt);
    cudaGetSymbolAddress((void**)&v,   g_v);
    cudaGetSymbolAddress((void**)&s16, g_s);
    cudaGetSymbolAddress((void**)&av,  g_av);

    cvt_kernel<<<(3 * CC * CC + 255) / 256, 256>>>(w_qkv, wq, 3 * CC * CC);
    cvt_kernel<<<(CC * CC + 255) / 256, 256>>>(w_proj, wp, CC * CC);

    gn_kernel<<<BB * 32, 256, 65536>>>(x, gamma, beta);

    // QK: D[n][o] = sum_c xn_t[n][c] * Wqk[o][c] + b_qkv[o]   (M=1024, N=1024, K=512)
    gemm_hh<0><<<dim3(8, 8, BB), 256, SMEM_BYTES>>>(
        xn, (size_t)NN_ * CC, CC,
        wq, 0, CC, CC,
        qkt, nullptr, (size_t)NN_ * NN_, NN_, b_qkv, nullptr);

    // V: D[o][n] = sum_c Wv[o][c] * xn_t[n][c] + b_qkv[1024+o]  (M=512, N=1024, K=512)
    gemm_hh<1><<<dim3(8, 4, BB), 256, SMEM_BYTES>>>(
        wq + (size_t)2 * CC * CC, 0, CC,
        xn, (size_t)NN_ * CC, CC, CC,
        v, nullptr, (size_t)CC * NN_, NN_, b_qkv + 2 * CC, nullptr);

    // Scores: S16[i][j] = SCALE * sum_c q_t[i][c] * k_t[j][c]   (M=1024, N=1024, K=512)
    gemm_hh<2><<<dim3(8, 8, BB), 256, SMEM_BYTES>>>(
        qkt, (size_t)NN_ * NN_, NN_,
        qkt + CC, (size_t)NN_ * NN_, NN_, CC,
        s16, nullptr, (size_t)NN_ * NN_, NN_, nullptr, nullptr);

    // Fused softmax + AV: av_t[i][c] = softmax_j(S16[i][:]) . V[c][:]
    av_fused<<<dim3(4, 8, BB), 256, SMEM_BYTES>>>(s16, v, av);

    // Proj: y[o][n] = x[o][n] + b_proj[o] + sum_c Wp[o][c] * av_t[n][c] (M=512, N=1024, K=512)
    gemm_hh<4><<<dim3(8, 4, BB), 256, SMEM_BYTES>>>(
        wp, 0, CC,
        av, (size_t)NN_ * CC, CC, CC,
        nullptr, y, (size_t)CC * NN_, NN_, b_proj, x);
}

// round 8
// speedup vs baseline: 1.0441x; 1.0441x over previous
#include <cuda_runtime.h>
#include <cuda_fp16.h>
#include <math.h>
#include <stdint.h>

// Problem constants: B=16, C=512, H=W=32, GROUPS=32
#define BB   16
#define CC   512
#define NN_  1024
#define CG   16
#define SCALE 0.044194173824159216f   // 512^-0.5

// ---------------------------------------------------------------------------
// Scratch (device globals)
// ---------------------------------------------------------------------------
__device__ __align__(128) __half g_xn [(size_t)BB * NN_ * CC];   // xn_t [b][n][c]
__device__ __align__(128) __half g_wq [(size_t)3 * CC * CC];     // w_qkv fp16
__device__ __align__(128) __half g_wp [(size_t)CC * CC];         // w_proj fp16
__device__ __align__(128) __half g_qkt[(size_t)BB * NN_ * NN_];  // [b][n][o] (q|k)
__device__ __align__(128) __half g_v  [(size_t)BB * CC * NN_];   // v [b][c][n]
__device__ __align__(128) __half g_s  [(size_t)BB * NN_ * NN_];  // scaled scores fp16
__device__ __align__(128) __half g_a  [(size_t)BB * NN_ * NN_];  // attn fp16
__device__ __align__(128) __half g_av [(size_t)BB * NN_ * CC];   // av_t [b][n][c]

// ---------------------------------------------------------------------------
// Helpers (base-target sm_80+ only)
// ---------------------------------------------------------------------------
__device__ __forceinline__ uint32_t smem_u32(const void* p) {
    uint32_t a;
    asm("{ .reg .u64 t; cvta.to.shared.u64 t, %1; cvt.u32.u64 %0, t; }" : "=r"(a) : "l"(p));
    return a;
}
__device__ __forceinline__ void ldsm4(uint32_t (&r)[4], uint32_t addr) {
    asm volatile("ldmatrix.sync.aligned.m8n8.x4.shared.b16 {%0,%1,%2,%3}, [%4];"
        : "=r"(r[0]), "=r"(r[1]), "=r"(r[2]), "=r"(r[3]) : "r"(addr));
}
__device__ __forceinline__ void ldsm2(uint32_t (&r)[2], uint32_t addr) {
    asm volatile("ldmatrix.sync.aligned.m8n8.x2.shared.b16 {%0,%1}, [%2];"
        : "=r"(r[0]), "=r"(r[1]) : "r"(addr));
}
__device__ __forceinline__ void mma16816(float (&c)[4], const uint32_t (&a)[4],
                                         const uint32_t (&b)[2]) {
    asm volatile("mma.sync.aligned.m16n8k16.row.col.f32.f16.f16.f32 "
        "{%0,%1,%2,%3}, {%4,%5,%6,%7}, {%8,%9}, {%0,%1,%2,%3};"
        : "+f"(c[0]), "+f"(c[1]), "+f"(c[2]), "+f"(c[3])
        : "r"(a[0]), "r"(a[1]), "r"(a[2]), "r"(a[3]), "r"(b[0]), "r"(b[1]));
}
__device__ __forceinline__ void cp16(uint32_t dst, const void* src) {
    asm volatile("cp.async.cg.shared.global [%0], [%1], 16;" :: "r"(dst), "l"(src));
}
__device__ __forceinline__ void cp_commit() {
    asm volatile("cp.async.commit_group;" ::: "memory");
}
template<int N> __device__ __forceinline__ void cp_wait() {
    asm volatile("cp.async.wait_group %0;" :: "n"(N) : "memory");
}

// ---------------------------------------------------------------------------
// fp32 -> fp16 convert
// ---------------------------------------------------------------------------
__global__ void cvt_kernel(const float* __restrict__ src, __half* __restrict__ dst, int n) {
    int i = blockIdx.x * blockDim.x + threadIdx.x;
    if (i < n) dst[i] = __float2half_rn(src[i]);
}

// ---------------------------------------------------------------------------
// GroupNorm -> transposed fp16 output xn_t[b][n][c]
// ---------------------------------------------------------------------------
__global__ void gn_kernel(const float* __restrict__ x,
                          const float* __restrict__ gamma,
                          const float* __restrict__ beta) {
    extern __shared__ float xs[];              // 16 ch x 1024 px
    const int b = blockIdx.x >> 5;
    const int g = blockIdx.x & 31;
    const size_t base = ((size_t)b * CC + (size_t)g * CG) * NN_;
    const float4* __restrict__ x4 = (const float4*)(x + base);

    float s = 0.f, s2 = 0.f;
    for (int i = threadIdx.x; i < CG * NN_ / 4; i += 256) {
        float4 v = x4[i];
        ((float4*)xs)[i] = v;
        s  += v.x + v.y + v.z + v.w;
        s2 += v.x * v.x + v.y * v.y + v.z * v.z + v.w * v.w;
    }
    #pragma unroll
    for (int o = 16; o; o >>= 1) {
        s  += __shfl_down_sync(0xffffffffu, s,  o);
        s2 += __shfl_down_sync(0xffffffffu, s2, o);
    }
    __shared__ float2 sh[8];
    __shared__ float sga[16], sbe[16];
    if ((threadIdx.x & 31) == 0) sh[threadIdx.x >> 5] = make_float2(s, s2);
    __syncthreads();
    if (threadIdx.x < 16) {
        float ts = 0.f, ts2 = 0.f;
        #pragma unroll
        for (int i = 0; i < 8; i++) { ts += sh[i].x; ts2 += sh[i].y; }
        const float inv = 1.f / (float)(CG * NN_);
        float mu  = ts * inv;
        float var = ts2 * inv - mu * mu;
        float rstd = rsqrtf(var + 1e-5f);
        int c = g * CG + threadIdx.x;
        float ga = gamma[c] * rstd;
        sga[threadIdx.x] = ga;
        sbe[threadIdx.x] = beta[c] - mu * ga;
    }
    __syncthreads();

    for (int n = threadIdx.x; n < NN_; n += 256) {
        __align__(16) __half hh[16];
        #pragma unroll
        for (int c = 0; c < 16; c++)
            hh[c] = __float2half_rn(xs[c * NN_ + n] * sga[c] + sbe[c]);
        size_t o = ((size_t)(b * NN_ + n)) * CC + g * CG;
        *(uint4*)(g_xn + o)     = *(uint4*)(hh);
        *(uint4*)(g_xn + o + 8) = *(uint4*)(hh + 8);
    }
}

// ---------------------------------------------------------------------------
// fp16 HMMA GEMM:  D[M,N] = sum_k A[m][k] * B[n][k]   (both K-major)
// 128x128 CTA tile, BK=64, 8 warps (64x32), 3-stage cp.async ring, 2 CTA/SM.
// EPI: 0=fp16+col bias, 1=fp16+row bias, 2=fp16*SCALE, 3=fp16, 4=fp32+row bias+resid
// ---------------------------------------------------------------------------
#define STAGE_BYTES 32768              // A 16KB + B 16KB
#define NSTAGE      3
#define SMEM_BYTES  (NSTAGE * STAGE_BYTES)

template<int EPI>
__global__ void __launch_bounds__(256, 2) gemm_hh(
    const __half* __restrict__ A, size_t aBatch, int ldA,
    const __half* __restrict__ B, size_t bBatch, int ldB,
    int K,
    __half* __restrict__ outH, float* __restrict__ outF,
    size_t oBatch, int ldO,
    const float* __restrict__ bias, const float* __restrict__ resid)
{
    extern __shared__ char smem[];
    const uint32_t sb = smem_u32(smem);

    const int tid = threadIdx.x, lane = tid & 31, wid = tid >> 5;
    const int wm = wid >> 2, wn = wid & 3;
    const int b  = blockIdx.z;
    const int m0 = blockIdx.y * 128, n0 = blockIdx.x * 128;

    const __half* srcA = A + (size_t)b * aBatch + (size_t)m0 * ldA;
    const __half* srcB = B + (size_t)b * bBatch + (size_t)n0 * ldB;

    float acc[4][4][4];
    #pragma unroll
    for (int i = 0; i < 4; i++)
        #pragma unroll
        for (int j = 0; j < 4; j++)
            #pragma unroll
            for (int q = 0; q < 4; q++) acc[i][j][q] = 0.f;

    const int T = K / 64;

    const int l_row = tid >> 1;
    const int l_g0  = (tid & 1) * 4;
    auto load_stage = [&](int t) {
        const int k0 = t * 64;
        const uint32_t sbuf = sb + (uint32_t)(t % NSTAGE) * STAGE_BYTES;
        const uint32_t rowOff = (uint32_t)l_row * 128;
        #pragma unroll
        for (int q = 0; q < 4; q++) {
            const int g = l_g0 + q;
            const uint32_t sw = (uint32_t)((g ^ (l_row & 7)) << 4);
            cp16(sbuf + rowOff + sw,          srcA + (size_t)l_row * ldA + k0 + g * 8);
            cp16(sbuf + 16384 + rowOff + sw,  srcB + (size_t)l_row * ldB + k0 + g * 8);
        }
    };

    const int arow = lane & 15;
    const int akhi = lane >> 4;
    const int brow = lane & 7;
    const int bkhi = (lane >> 3) & 1;
    const uint32_t aRowOff = (uint32_t)(wm * 64 + arow) * 128;
    const uint32_t bRowOff = (uint32_t)(wn * 32 + brow) * 128 + 16384u;

    load_stage(0); cp_commit();
    load_stage(1); cp_commit();

    for (int t = 0; t < T; t++) {
        cp_wait<1>();
        __syncthreads();
        if (t + 2 < T) load_stage(t + 2);
        cp_commit();

        const uint32_t sbuf = sb + (uint32_t)(t % NSTAGE) * STAGE_BYTES;
        #pragma unroll
        for (int k16 = 0; k16 < 4; k16++) {
            const uint32_t aSw = (uint32_t)(((k16 * 2 + akhi) ^ (arow & 7)) << 4);
            const uint32_t bSw = (uint32_t)(((k16 * 2 + bkhi) ^ brow) << 4);
            uint32_t af[4][4], bf[4][2];
            #pragma unroll
            for (int i = 0; i < 4; i++)
                ldsm4(af[i], sbuf + aRowOff + (uint32_t)(i * 16 * 128) + aSw);
            #pragma unroll
            for (int j = 0; j < 4; j++)
                ldsm2(bf[j], sbuf + bRowOff + (uint32_t)(j * 8 * 128) + bSw);
            #pragma unroll
            for (int i = 0; i < 4; i++)
                #pragma unroll
                for (int j = 0; j < 4; j++)
                    mma16816(acc[i][j], af[i], bf[j]);
        }
    }

    // epilogue
    const int rbase = m0 + wm * 64 + (lane >> 2);
    const int cbase = n0 + wn * 32 + (lane & 3) * 2;

    float bc0[4], bc1[4];
    if (EPI == 0) {
        #pragma unroll
        for (int j = 0; j < 4; j++) { bc0[j] = bias[cbase + j * 8]; bc1[j] = bias[cbase + j * 8 + 1]; }
    }

    #pragma unroll
    for (int i = 0; i < 4; i++) {
        const int row0 = rbase + i * 16, row1 = row0 + 8;
        float br0 = 0.f, br1 = 0.f;
        if (EPI == 1 || EPI == 4) { br0 = bias[row0]; br1 = bias[row1]; }
        #pragma unroll
        for (int j = 0; j < 4; j++) {
            const int col = cbase + j * 8;
            const size_t ob0 = (size_t)b * oBatch + (size_t)row0 * ldO + col;
            const size_t ob1 = (size_t)b * oBatch + (size_t)row1 * ldO + col;
            float v0 = acc[i][j][0], v1 = acc[i][j][1];
            float v2 = acc[i][j][2], v3 = acc[i][j][3];
            if (EPI == 2) {
                *(__half2*)(outH + ob0) = __floats2half2_rn(v0 * SCALE, v1 * SCALE);
                *(__half2*)(outH + ob1) = __floats2half2_rn(v2 * SCALE, v3 * SCALE);
            } else if (EPI == 4) {
                float2 r0 = *(const float2*)(resid + ob0);
                float2 r1 = *(const float2*)(resid + ob1);
                *(float2*)(outF + ob0) = make_float2(v0 + br0 + r0.x, v1 + br0 + r0.y);
                *(float2*)(outF + ob1) = make_float2(v2 + br1 + r1.x, v3 + br1 + r1.y);
            } else {
                if (EPI == 0) { v0 += bc0[j]; v1 += bc1[j]; v2 += bc0[j]; v3 += bc1[j]; }
                if (EPI == 1) { v0 += br0;    v1 += br0;    v2 += br1;    v3 += br1;   }
                *(__half2*)(outH + ob0) = __floats2half2_rn(v0, v1);
                *(__half2*)(outH + ob1) = __floats2half2_rn(v2, v3);
            }
        }
    }
}

// ---------------------------------------------------------------------------
// Softmax over rows of fp16 scores -> fp16 attn. 256 thr, 4 halves/thread.
// ---------------------------------------------------------------------------
__global__ void softmax_kernel() {
    const size_t rbase = (size_t)blockIdx.x * NN_;
    uint2 rv = *(const uint2*)(g_s + rbase + threadIdx.x * 4);
    float2 a0 = __half22float2(*(const __half2*)&rv.x);
    float2 a1 = __half22float2(*(const __half2*)&rv.y);

    float m = fmaxf(fmaxf(a0.x, a0.y), fmaxf(a1.x, a1.y));
    #pragma unroll
    for (int o = 16; o; o >>= 1) m = fmaxf(m, __shfl_xor_sync(0xffffffffu, m, o));
    __shared__ float shm[8], shs[8];
    if ((threadIdx.x & 31) == 0) shm[threadIdx.x >> 5] = m;
    __syncthreads();
    float M = shm[0];
    #pragma unroll
    for (int i = 1; i < 8; i++) M = fmaxf(M, shm[i]);

    a0.x = __expf(a0.x - M); a0.y = __expf(a0.y - M);
    a1.x = __expf(a1.x - M); a1.y = __expf(a1.y - M);
    float s = a0.x + a0.y + a1.x + a1.y;
    #pragma unroll
    for (int o = 16; o; o >>= 1) s += __shfl_xor_sync(0xffffffffu, s, o);
    if ((threadIdx.x & 31) == 0) shs[threadIdx.x >> 5] = s;
    __syncthreads();
    float S = 0.f;
    #pragma unroll
    for (int i = 0; i < 8; i++) S += shs[i];
    const float r = 1.f / S;

    __half2 h0 = __floats2half2_rn(a0.x * r, a0.y * r);
    __half2 h1 = __floats2half2_rn(a1.x * r, a1.y * r);
    uint2 wv;
    wv.x = *(const uint32_t*)&h0;
    wv.y = *(const uint32_t*)&h1;
    *(uint2*)(g_a + rbase + threadIdx.x * 4) = wv;
}

// ---------------------------------------------------------------------------
// Launch — two-stream graph: V GEMM + weight converts overlap the QK/scores path.
// Streams/events created once on the first (uncaptured) correctness call.
// ---------------------------------------------------------------------------
static cudaStream_t s2 = nullptr;
static cudaEvent_t evFork = nullptr, evFork2 = nullptr, evJoin = nullptr;

extern "C" void kernel_launch(void* const* d_in, const int* in_sizes, int n_in,
                              void* d_out, int out_size) {
    const float* x      = (const float*)d_in[0];
    const float* gamma  = (const float*)d_in[1];
    const float* beta   = (const float*)d_in[2];
    const float* w_qkv  = (const float*)d_in[3];
    const float* b_qkv  = (const float*)d_in[4];
    const float* w_proj = (const float*)d_in[5];
    const float* b_proj = (const float*)d_in[6];
    float* y = (float*)d_out;

    if (!s2) {
        cudaStreamCreateWithFlags(&s2, cudaStreamNonBlocking);
        cudaEventCreateWithFlags(&evFork,  cudaEventDisableTiming);
        cudaEventCreateWithFlags(&evFork2, cudaEventDisableTiming);
        cudaEventCreateWithFlags(&evJoin,  cudaEventDisableTiming);
    }

    cudaFuncSetAttribute(gn_kernel,  cudaFuncAttributeMaxDynamicSharedMemorySize, 65536);
    cudaFuncSetAttribute(gemm_hh<0>, cudaFuncAttributeMaxDynamicSharedMemorySize, SMEM_BYTES);
    cudaFuncSetAttribute(gemm_hh<1>, cudaFuncAttributeMaxDynamicSharedMemorySize, SMEM_BYTES);
    cudaFuncSetAttribute(gemm_hh<2>, cudaFuncAttributeMaxDynamicSharedMemorySize, SMEM_BYTES);
    cudaFuncSetAttribute(gemm_hh<3>, cudaFuncAttributeMaxDynamicSharedMemorySize, SMEM_BYTES);
    cudaFuncSetAttribute(gemm_hh<4>, cudaFuncAttributeMaxDynamicSharedMemorySize, SMEM_BYTES);

    __half *xn, *wq, *wp, *qkt, *v, *s16, *a, *av;
    cudaGetSymbolAddress((void**)&xn,  g_xn);
    cudaGetSymbolAddress((void**)&wq,  g_wq);
    cudaGetSymbolAddress((void**)&wp,  g_wp);
    cudaGetSymbolAddress((void**)&qkt, g_qkt);
    cudaGetSymbolAddress((void**)&v,   g_v);
    cudaGetSymbolAddress((void**)&s16, g_s);
    cudaGetSymbolAddress((void**)&a,   g_a);
    cudaGetSymbolAddress((void**)&av,  g_av);

    // fork: s2 handles weight converts (independent of GN)
    cudaEventRecord(evFork, 0);
    cudaStreamWaitEvent(s2, evFork, 0);

    cvt_kernel<<<(3 * CC * CC + 255) / 256, 256, 0, s2>>>(w_qkv, wq, 3 * CC * CC);
    cvt_kernel<<<(CC * CC + 255) / 256, 256, 0, s2>>>(w_proj, wp, CC * CC);

    // main: GroupNorm
    gn_kernel<<<BB * 32, 256, 65536>>>(x, gamma, beta);

    // s2 must also see GN output before the V GEMM
    cudaEventRecord(evFork2, 0);
    cudaStreamWaitEvent(s2, evFork2, 0);

    // s2: V GEMM (independent of QK/scores/softmax)
    // V: D[o][n] = sum_c Wv[o][c] * xn_t[n][c] + b_qkv[1024+o]  (M=512, N=1024, K=512)
    gemm_hh<1><<<dim3(8, 4, BB), 256, SMEM_BYTES, s2>>>(
        wq + (size_t)2 * CC * CC, 0, CC,
        xn, (size_t)NN_ * CC, CC, CC,
        v, nullptr, (size_t)CC * NN_, NN_, b_qkv + 2 * CC, nullptr);
    cudaEventRecord(evJoin, s2);

    // main: QK GEMM (needs wq from s2? -> wq convert finishes long before QK reads it;
    // but capture requires explicit ordering: QK depends on cvt via evFork2? No —
    // enforce it: QK launched after evFork2 record only orders GN. To be safe, QK
    // waits on nothing extra; instead make cvt ordering explicit by putting the
    // QK-dependency join here.)
    // NOTE: wq is produced on s2; QK on stream 0 must wait for it.
    cudaStreamWaitEvent(0, evJoin, 0);   // joins cvt+V; V also done before AV later

    // QK: D[n][o] = sum_c xn_t[n][c] * Wqk[o][c] + b_qkv[o]   (M=1024, N=1024, K=512)
    gemm_hh<0><<<dim3(8, 8, BB), 256, SMEM_BYTES>>>(
        xn, (size_t)NN_ * CC, CC,
        wq, 0, CC, CC,
        qkt, nullptr, (size_t)NN_ * NN_, NN_, b_qkv, nullptr);

    // Scores: S16[i][j] = SCALE * sum_c q_t[i][c] * k_t[j][c]   (M=1024, N=1024, K=512)
    gemm_hh<2><<<dim3(8, 8, BB), 256, SMEM_BYTES>>>(
        qkt, (size_t)NN_ * NN_, NN_,
        qkt + CC, (size_t)NN_ * NN_, NN_, CC,
        s16, nullptr, (size_t)NN_ * NN_, NN_, nullptr, nullptr);

    softmax_kernel<<<BB * NN_, 256>>>();

    // AV: D[i][c] = sum_j attn[i][j] * v[c][j]                  (M=1024, N=512, K=1024)
    gemm_hh<3><<<dim3(4, 8, BB), 256, SMEM_BYTES>>>(
        a, (size_t)NN_ * NN_, NN_,
        v, (size_t)CC * NN_, NN_, NN_,
        av, nullptr, (size_t)NN_ * CC, CC, nullptr, nullptr);

    // Proj: y[o][n] = x[o][n] + b_proj[o] + sum_c Wp[o][c] * av_t[n][c] (M=512, N=1024, K=512)
    gemm_hh<4><<<dim3(8, 4, BB), 256, SMEM_BYTES>>>(
        wp, 0, CC,
        av, (size_t)NN_ * CC, CC, CC,
        nullptr, y, (size_t)CC * NN_, NN_, b_proj, x);
}

// round 9
// speedup vs baseline: 1.0991x; 1.0527x over previous
#include <cuda_runtime.h>
#include <cuda_fp16.h>
#include <math.h>
#include <stdint.h>

// Problem constants: B=16, C=512, H=W=32, GROUPS=32
#define BB   16
#define CC   512
#define NN_  1024
#define CG   16
#define SCALE 0.044194173824159216f   // 512^-0.5

// ---------------------------------------------------------------------------
// Scratch (device globals)
// ---------------------------------------------------------------------------
__device__ __align__(128) __half g_xn [(size_t)BB * NN_ * CC];   // xn_t [b][n][c]
__device__ __align__(128) __half g_wq [(size_t)3 * CC * CC];     // w_qkv fp16
__device__ __align__(128) __half g_wp [(size_t)CC * CC];         // w_proj fp16
__device__ __align__(128) __half g_qkt[(size_t)BB * NN_ * NN_];  // [b][n][o] (q|k)
__device__ __align__(128) __half g_v  [(size_t)BB * CC * NN_];   // v [b][c][n]
__device__ __align__(128) __half g_s  [(size_t)BB * NN_ * NN_];  // scaled scores fp16
__device__ __align__(128) __half g_a  [(size_t)BB * NN_ * NN_];  // attn fp16
__device__ __align__(128) __half g_av [(size_t)BB * NN_ * CC];   // av_t [b][n][c]

// ---------------------------------------------------------------------------
// Helpers (base-target sm_80+ only)
// ---------------------------------------------------------------------------
__device__ __forceinline__ uint32_t smem_u32(const void* p) {
    uint32_t a;
    asm("{ .reg .u64 t; cvta.to.shared.u64 t, %1; cvt.u32.u64 %0, t; }" : "=r"(a) : "l"(p));
    return a;
}
__device__ __forceinline__ void ldsm4(uint32_t (&r)[4], uint32_t addr) {
    asm volatile("ldmatrix.sync.aligned.m8n8.x4.shared.b16 {%0,%1,%2,%3}, [%4];"
        : "=r"(r[0]), "=r"(r[1]), "=r"(r[2]), "=r"(r[3]) : "r"(addr));
}
__device__ __forceinline__ void ldsm2(uint32_t (&r)[2], uint32_t addr) {
    asm volatile("ldmatrix.sync.aligned.m8n8.x2.shared.b16 {%0,%1}, [%2];"
        : "=r"(r[0]), "=r"(r[1]) : "r"(addr));
}
__device__ __forceinline__ void mma16816(float (&c)[4], const uint32_t (&a)[4],
                                         const uint32_t (&b)[2]) {
    asm volatile("mma.sync.aligned.m16n8k16.row.col.f32.f16.f16.f32 "
        "{%0,%1,%2,%3}, {%4,%5,%6,%7}, {%8,%9}, {%0,%1,%2,%3};"
        : "+f"(c[0]), "+f"(c[1]), "+f"(c[2]), "+f"(c[3])
        : "r"(a[0]), "r"(a[1]), "r"(a[2]), "r"(a[3]), "r"(b[0]), "r"(b[1]));
}
__device__ __forceinline__ void cp16(uint32_t dst, const void* src) {
    asm volatile("cp.async.cg.shared.global [%0], [%1], 16;" :: "r"(dst), "l"(src));
}
__device__ __forceinline__ void cp_commit() {
    asm volatile("cp.async.commit_group;" ::: "memory");
}
template<int N> __device__ __forceinline__ void cp_wait() {
    asm volatile("cp.async.wait_group %0;" :: "n"(N) : "memory");
}

// ---------------------------------------------------------------------------
// fp32 -> fp16 convert
// ---------------------------------------------------------------------------
__global__ void cvt_kernel(const float* __restrict__ src, __half* __restrict__ dst, int n) {
    int i = blockIdx.x * blockDim.x + threadIdx.x;
    if (i < n) dst[i] = __float2half_rn(src[i]);
}

// ---------------------------------------------------------------------------
// GroupNorm -> transposed fp16 output xn_t[b][n][c]
// ---------------------------------------------------------------------------
__global__ void gn_kernel(const float* __restrict__ x,
                          const float* __restrict__ gamma,
                          const float* __restrict__ beta) {
    extern __shared__ float xs[];              // 16 ch x 1024 px
    const int b = blockIdx.x >> 5;
    const int g = blockIdx.x & 31;
    const size_t base = ((size_t)b * CC + (size_t)g * CG) * NN_;
    const float4* __restrict__ x4 = (const float4*)(x + base);

    float s = 0.f, s2 = 0.f;
    for (int i = threadIdx.x; i < CG * NN_ / 4; i += 256) {
        float4 v = x4[i];
        ((float4*)xs)[i] = v;
        s  += v.x + v.y + v.z + v.w;
        s2 += v.x * v.x + v.y * v.y + v.z * v.z + v.w * v.w;
    }
    #pragma unroll
    for (int o = 16; o; o >>= 1) {
        s  += __shfl_down_sync(0xffffffffu, s,  o);
        s2 += __shfl_down_sync(0xffffffffu, s2, o);
    }
    __shared__ float2 sh[8];
    __shared__ float sga[16], sbe[16];
    if ((threadIdx.x & 31) == 0) sh[threadIdx.x >> 5] = make_float2(s, s2);
    __syncthreads();
    if (threadIdx.x < 16) {
        float ts = 0.f, ts2 = 0.f;
        #pragma unroll
        for (int i = 0; i < 8; i++) { ts += sh[i].x; ts2 += sh[i].y; }
        const float inv = 1.f / (float)(CG * NN_);
        float mu  = ts * inv;
        float var = ts2 * inv - mu * mu;
        float rstd = rsqrtf(var + 1e-5f);
        int c = g * CG + threadIdx.x;
        float ga = gamma[c] * rstd;
        sga[threadIdx.x] = ga;
        sbe[threadIdx.x] = beta[c] - mu * ga;
    }
    __syncthreads();

    for (int n = threadIdx.x; n < NN_; n += 256) {
        __align__(16) __half hh[16];
        #pragma unroll
        for (int c = 0; c < 16; c++)
            hh[c] = __float2half_rn(xs[c * NN_ + n] * sga[c] + sbe[c]);
        size_t o = ((size_t)(b * NN_ + n)) * CC + g * CG;
        *(uint4*)(g_xn + o)     = *(uint4*)(hh);
        *(uint4*)(g_xn + o + 8) = *(uint4*)(hh + 8);
    }
}

// ---------------------------------------------------------------------------
// fp16 HMMA GEMM:  D[M,N] = sum_k A[m][k] * B[n][k]   (both K-major)
// 128x128 CTA tile, BK=64, 8 warps (64x32), 3-stage cp.async ring, 2 CTA/SM.
// EPI: 0=fp16+col bias, 1=fp16+row bias, 2=fp16*SCALE, 3=fp16, 4=fp32+row bias+resid
// ---------------------------------------------------------------------------
#define STAGE_BYTES 32768              // A 16KB + B 16KB
#define NSTAGE      3
#define SMEM_BYTES  (NSTAGE * STAGE_BYTES)

template<int EPI>
__global__ void __launch_bounds__(256, 2) gemm_hh(
    const __half* __restrict__ A, size_t aBatch, int ldA,
    const __half* __restrict__ B, size_t bBatch, int ldB,
    int K,
    __half* __restrict__ outH, float* __restrict__ outF,
    size_t oBatch, int ldO,
    const float* __restrict__ bias, const float* __restrict__ resid)
{
    extern __shared__ char smem[];
    const uint32_t sb = smem_u32(smem);

    const int tid = threadIdx.x, lane = tid & 31, wid = tid >> 5;
    const int wm = wid >> 2, wn = wid & 3;
    const int b  = blockIdx.z;
    const int m0 = blockIdx.y * 128, n0 = blockIdx.x * 128;

    const __half* srcA = A + (size_t)b * aBatch + (size_t)m0 * ldA;
    const __half* srcB = B + (size_t)b * bBatch + (size_t)n0 * ldB;

    float acc[4][4][4];
    #pragma unroll
    for (int i = 0; i < 4; i++)
        #pragma unroll
        for (int j = 0; j < 4; j++)
            #pragma unroll
            for (int q = 0; q < 4; q++) acc[i][j][q] = 0.f;

    const int T = K / 64;

    const int l_row = tid >> 1;
    const int l_g0  = (tid & 1) * 4;
    auto load_stage = [&](int t) {
        const int k0 = t * 64;
        const uint32_t sbuf = sb + (uint32_t)(t % NSTAGE) * STAGE_BYTES;
        const uint32_t rowOff = (uint32_t)l_row * 128;
        #pragma unroll
        for (int q = 0; q < 4; q++) {
            const int g = l_g0 + q;
            const uint32_t sw = (uint32_t)((g ^ (l_row & 7)) << 4);
            cp16(sbuf + rowOff + sw,          srcA + (size_t)l_row * ldA + k0 + g * 8);
            cp16(sbuf + 16384 + rowOff + sw,  srcB + (size_t)l_row * ldB + k0 + g * 8);
        }
    };

    const int arow = lane & 15;
    const int akhi = lane >> 4;
    const int brow = lane & 7;
    const int bkhi = (lane >> 3) & 1;
    const uint32_t aRowOff = (uint32_t)(wm * 64 + arow) * 128;
    const uint32_t bRowOff = (uint32_t)(wn * 32 + brow) * 128 + 16384u;

    load_stage(0); cp_commit();
    load_stage(1); cp_commit();

    for (int t = 0; t < T; t++) {
        cp_wait<1>();
        __syncthreads();
        if (t + 2 < T) load_stage(t + 2);
        cp_commit();

        const uint32_t sbuf = sb + (uint32_t)(t % NSTAGE) * STAGE_BYTES;
        #pragma unroll
        for (int k16 = 0; k16 < 4; k16++) {
            const uint32_t aSw = (uint32_t)(((k16 * 2 + akhi) ^ (arow & 7)) << 4);
            const uint32_t bSw = (uint32_t)(((k16 * 2 + bkhi) ^ brow) << 4);
            uint32_t af[4][4], bf[4][2];
            #pragma unroll
            for (int i = 0; i < 4; i++)
                ldsm4(af[i], sbuf + aRowOff + (uint32_t)(i * 16 * 128) + aSw);
            #pragma unroll
            for (int j = 0; j < 4; j++)
                ldsm2(bf[j], sbuf + bRowOff + (uint32_t)(j * 8 * 128) + bSw);
            #pragma unroll
            for (int i = 0; i < 4; i++)
                #pragma unroll
                for (int j = 0; j < 4; j++)
                    mma16816(acc[i][j], af[i], bf[j]);
        }
    }

    // epilogue
    const int rbase = m0 + wm * 64 + (lane >> 2);
    const int cbase = n0 + wn * 32 + (lane & 3) * 2;

    float bc0[4], bc1[4];
    if (EPI == 0) {
        #pragma unroll
        for (int j = 0; j < 4; j++) { bc0[j] = bias[cbase + j * 8]; bc1[j] = bias[cbase + j * 8 + 1]; }
    }

    #pragma unroll
    for (int i = 0; i < 4; i++) {
        const int row0 = rbase + i * 16, row1 = row0 + 8;
        float br0 = 0.f, br1 = 0.f;
        if (EPI == 1 || EPI == 4) { br0 = bias[row0]; br1 = bias[row1]; }
        #pragma unroll
        for (int j = 0; j < 4; j++) {
            const int col = cbase + j * 8;
            const size_t ob0 = (size_t)b * oBatch + (size_t)row0 * ldO + col;
            const size_t ob1 = (size_t)b * oBatch + (size_t)row1 * ldO + col;
            float v0 = acc[i][j][0], v1 = acc[i][j][1];
            float v2 = acc[i][j][2], v3 = acc[i][j][3];
            if (EPI == 2) {
                *(__half2*)(outH + ob0) = __floats2half2_rn(v0 * SCALE, v1 * SCALE);
                *(__half2*)(outH + ob1) = __floats2half2_rn(v2 * SCALE, v3 * SCALE);
            } else if (EPI == 4) {
                float2 r0 = *(const float2*)(resid + ob0);
                float2 r1 = *(const float2*)(resid + ob1);
                *(float2*)(outF + ob0) = make_float2(v0 + br0 + r0.x, v1 + br0 + r0.y);
                *(float2*)(outF + ob1) = make_float2(v2 + br1 + r1.x, v3 + br1 + r1.y);
            } else {
                if (EPI == 0) { v0 += bc0[j]; v1 += bc1[j]; v2 += bc0[j]; v3 += bc1[j]; }
                if (EPI == 1) { v0 += br0;    v1 += br0;    v2 += br1;    v3 += br1;   }
                *(__half2*)(outH + ob0) = __floats2half2_rn(v0, v1);
                *(__half2*)(outH + ob1) = __floats2half2_rn(v2, v3);
            }
        }
    }
}

// ---------------------------------------------------------------------------
// Softmax over rows of fp16 scores -> fp16 attn. 256 thr, 4 halves/thread.
// ---------------------------------------------------------------------------
__global__ void softmax_kernel() {
    const size_t rbase = (size_t)blockIdx.x * NN_;
    uint2 rv = *(const uint2*)(g_s + rbase + threadIdx.x * 4);
    float2 a0 = __half22float2(*(const __half2*)&rv.x);
    float2 a1 = __half22float2(*(const __half2*)&rv.y);

    float m = fmaxf(fmaxf(a0.x, a0.y), fmaxf(a1.x, a1.y));
    #pragma unroll
    for (int o = 16; o; o >>= 1) m = fmaxf(m, __shfl_xor_sync(0xffffffffu, m, o));
    __shared__ float shm[8], shs[8];
    if ((threadIdx.x & 31) == 0) shm[threadIdx.x >> 5] = m;
    __syncthreads();
    float M = shm[0];
    #pragma unroll
    for (int i = 1; i < 8; i++) M = fmaxf(M, shm[i]);

    a0.x = __expf(a0.x - M); a0.y = __expf(a0.y - M);
    a1.x = __expf(a1.x - M); a1.y = __expf(a1.y - M);
    float s = a0.x + a0.y + a1.x + a1.y;
    #pragma unroll
    for (int o = 16; o; o >>= 1) s += __shfl_xor_sync(0xffffffffu, s, o);
    if ((threadIdx.x & 31) == 0) shs[threadIdx.x >> 5] = s;
    __syncthreads();
    float S = 0.f;
    #pragma unroll
    for (int i = 0; i < 8; i++) S += shs[i];
    const float r = 1.f / S;

    __half2 h0 = __floats2half2_rn(a0.x * r, a0.y * r);
    __half2 h1 = __floats2half2_rn(a1.x * r, a1.y * r);
    uint2 wv;
    wv.x = *(const uint32_t*)&h0;
    wv.y = *(const uint32_t*)&h1;
    *(uint2*)(g_a + rbase + threadIdx.x * 4) = wv;
}

// ---------------------------------------------------------------------------
// Launch — proper fork/join: V GEMM on s2 overlaps QK+scores+softmax on s0.
// ---------------------------------------------------------------------------
static cudaStream_t s2 = nullptr;
static cudaEvent_t evFork = nullptr, evGN = nullptr, evCvt = nullptr, evV = nullptr;

extern "C" void kernel_launch(void* const* d_in, const int* in_sizes, int n_in,
                              void* d_out, int out_size) {
    const float* x      = (const float*)d_in[0];
    const float* gamma  = (const float*)d_in[1];
    const float* beta   = (const float*)d_in[2];
    const float* w_qkv  = (const float*)d_in[3];
    const float* b_qkv  = (const float*)d_in[4];
    const float* w_proj = (const float*)d_in[5];
    const float* b_proj = (const float*)d_in[6];
    float* y = (float*)d_out;

    if (!s2) {
        cudaStreamCreateWithFlags(&s2, cudaStreamNonBlocking);
        cudaEventCreateWithFlags(&evFork, cudaEventDisableTiming);
        cudaEventCreateWithFlags(&evGN,   cudaEventDisableTiming);
        cudaEventCreateWithFlags(&evCvt,  cudaEventDisableTiming);
        cudaEventCreateWithFlags(&evV,    cudaEventDisableTiming);
    }

    cudaFuncSetAttribute(gn_kernel,  cudaFuncAttributeMaxDynamicSharedMemorySize, 65536);
    cudaFuncSetAttribute(gemm_hh<0>, cudaFuncAttributeMaxDynamicSharedMemorySize, SMEM_BYTES);
    cudaFuncSetAttribute(gemm_hh<1>, cudaFuncAttributeMaxDynamicSharedMemorySize, SMEM_BYTES);
    cudaFuncSetAttribute(gemm_hh<2>, cudaFuncAttributeMaxDynamicSharedMemorySize, SMEM_BYTES);
    cudaFuncSetAttribute(gemm_hh<3>, cudaFuncAttributeMaxDynamicSharedMemorySize, SMEM_BYTES);
    cudaFuncSetAttribute(gemm_hh<4>, cudaFuncAttributeMaxDynamicSharedMemorySize, SMEM_BYTES);

    __half *xn, *wq, *wp, *qkt, *v, *s16, *a, *av;
    cudaGetSymbolAddress((void**)&xn,  g_xn);
    cudaGetSymbolAddress((void**)&wq,  g_wq);
    cudaGetSymbolAddress((void**)&wp,  g_wp);
    cudaGetSymbolAddress((void**)&qkt, g_qkt);
    cudaGetSymbolAddress((void**)&v,   g_v);
    cudaGetSymbolAddress((void**)&s16, g_s);
    cudaGetSymbolAddress((void**)&a,   g_a);
    cudaGetSymbolAddress((void**)&av,  g_av);

    // fork: s2 converts weights while s0 runs GroupNorm
    cudaEventRecord(evFork, 0);
    cudaStreamWaitEvent(s2, evFork, 0);

    cvt_kernel<<<(3 * CC * CC + 255) / 256, 256, 0, s2>>>(w_qkv, wq, 3 * CC * CC);
    cvt_kernel<<<(CC * CC + 255) / 256, 256, 0, s2>>>(w_proj, wp, CC * CC);
    cudaEventRecord(evCvt, s2);

    // s0: GroupNorm
    gn_kernel<<<BB * 32, 256, 65536>>>(x, gamma, beta);
    cudaEventRecord(evGN, 0);

    // s2: V GEMM after GN (cvt already ordered on s2); overlaps QK+scores on s0
    cudaStreamWaitEvent(s2, evGN, 0);
    gemm_hh<1><<<dim3(8, 4, BB), 256, SMEM_BYTES, s2>>>(
        wq + (size_t)2 * CC * CC, 0, CC,
        xn, (size_t)NN_ * CC, CC, CC,
        v, nullptr, (size_t)CC * NN_, NN_, b_qkv + 2 * CC, nullptr);
    cudaEventRecord(evV, s2);

    // s0: QK needs wq (cvt on s2) — wait only for cvt, not V
    cudaStreamWaitEvent(0, evCvt, 0);
    gemm_hh<0><<<dim3(8, 8, BB), 256, SMEM_BYTES>>>(
        xn, (size_t)NN_ * CC, CC,
        wq, 0, CC, CC,
        qkt, nullptr, (size_t)NN_ * NN_, NN_, b_qkv, nullptr);

    // s0: scores
    gemm_hh<2><<<dim3(8, 8, BB), 256, SMEM_BYTES>>>(
        qkt, (size_t)NN_ * NN_, NN_,
        qkt + CC, (size_t)NN_ * NN_, NN_, CC,
        s16, nullptr, (size_t)NN_ * NN_, NN_, nullptr, nullptr);

    softmax_kernel<<<BB * NN_, 256>>>();

    // s0: AV consumes g_v — join V here
    cudaStreamWaitEvent(0, evV, 0);
    gemm_hh<3><<<dim3(4, 8, BB), 256, SMEM_BYTES>>>(
        a, (size_t)NN_ * NN_, NN_,
        v, (size_t)CC * NN_, NN_, NN_,
        av, nullptr, (size_t)NN_ * CC, CC, nullptr, nullptr);

    // s0: proj + residual
    gemm_hh<4><<<dim3(8, 4, BB), 256, SMEM_BYTES>>>(
        wp, 0, CC,
        av, (size_t)NN_ * CC, CC, CC,
        nullptr, y, (size_t)CC * NN_, NN_, b_proj, x);
}

// round 10
// speedup vs baseline: 1.1753x; 1.0693x over previous
#include <cuda_runtime.h>
#include <cuda_fp16.h>
#include <math.h>
#include <stdint.h>

// Problem constants: B=16, C=512, H=W=32, GROUPS=32
#define BB   16
#define CC   512
#define NN_  1024
#define CG   16
#define SCALE 0.044194173824159216f   // 512^-0.5

// ---------------------------------------------------------------------------
// Scratch (device globals)
// ---------------------------------------------------------------------------
__device__ __align__(128) __half g_xn [(size_t)BB * NN_ * CC];   // xn_t [b][n][c]
__device__ __align__(128) __half g_wq [(size_t)3 * CC * CC];     // w_qkv fp16
__device__ __align__(128) __half g_wp [(size_t)CC * CC];         // w_proj fp16
__device__ __align__(128) __half g_qkt[(size_t)BB * NN_ * NN_];  // [b][n][o] (q|k)
__device__ __align__(128) __half g_v  [(size_t)BB * CC * NN_];   // v [b][c][n]
__device__ __align__(128) __half g_s  [(size_t)BB * NN_ * NN_];  // scaled scores fp16
__device__ __align__(128) __half g_a  [(size_t)BB * NN_ * NN_];  // attn fp16
__device__ __align__(128) __half g_av [(size_t)BB * NN_ * CC];   // av_t [b][n][c]

// ---------------------------------------------------------------------------
// Helpers (base-target sm_80+ only)
// ---------------------------------------------------------------------------
__device__ __forceinline__ uint32_t smem_u32(const void* p) {
    uint32_t a;
    asm("{ .reg .u64 t; cvta.to.shared.u64 t, %1; cvt.u32.u64 %0, t; }" : "=r"(a) : "l"(p));
    return a;
}
__device__ __forceinline__ void ldsm4(uint32_t (&r)[4], uint32_t addr) {
    asm volatile("ldmatrix.sync.aligned.m8n8.x4.shared.b16 {%0,%1,%2,%3}, [%4];"
        : "=r"(r[0]), "=r"(r[1]), "=r"(r[2]), "=r"(r[3]) : "r"(addr));
}
__device__ __forceinline__ void mma16816(float (&c)[4], const uint32_t (&a)[4],
                                         const uint32_t b0, const uint32_t b1) {
    asm volatile("mma.sync.aligned.m16n8k16.row.col.f32.f16.f16.f32 "
        "{%0,%1,%2,%3}, {%4,%5,%6,%7}, {%8,%9}, {%0,%1,%2,%3};"
        : "+f"(c[0]), "+f"(c[1]), "+f"(c[2]), "+f"(c[3])
        : "r"(a[0]), "r"(a[1]), "r"(a[2]), "r"(a[3]), "r"(b0), "r"(b1));
}
__device__ __forceinline__ void cp16(uint32_t dst, const void* src) {
    asm volatile("cp.async.cg.shared.global [%0], [%1], 16;" :: "r"(dst), "l"(src));
}
__device__ __forceinline__ void cp_commit() {
    asm volatile("cp.async.commit_group;" ::: "memory");
}
template<int N> __device__ __forceinline__ void cp_wait() {
    asm volatile("cp.async.wait_group %0;" :: "n"(N) : "memory");
}

// ---------------------------------------------------------------------------
// fp32 -> fp16 convert
// ---------------------------------------------------------------------------
__global__ void cvt_kernel(const float* __restrict__ src, __half* __restrict__ dst, int n) {
    int i = blockIdx.x * blockDim.x + threadIdx.x;
    if (i < n) dst[i] = __float2half_rn(src[i]);
}

// ---------------------------------------------------------------------------
// GroupNorm -> transposed fp16 output xn_t[b][n][c]
// ---------------------------------------------------------------------------
__global__ void gn_kernel(const float* __restrict__ x,
                          const float* __restrict__ gamma,
                          const float* __restrict__ beta) {
    extern __shared__ float xs[];              // 16 ch x 1024 px
    const int b = blockIdx.x >> 5;
    const int g = blockIdx.x & 31;
    const size_t base = ((size_t)b * CC + (size_t)g * CG) * NN_;
    const float4* __restrict__ x4 = (const float4*)(x + base);

    float s = 0.f, s2 = 0.f;
    for (int i = threadIdx.x; i < CG * NN_ / 4; i += 256) {
        float4 v = x4[i];
        ((float4*)xs)[i] = v;
        s  += v.x + v.y + v.z + v.w;
        s2 += v.x * v.x + v.y * v.y + v.z * v.z + v.w * v.w;
    }
    #pragma unroll
    for (int o = 16; o; o >>= 1) {
        s  += __shfl_down_sync(0xffffffffu, s,  o);
        s2 += __shfl_down_sync(0xffffffffu, s2, o);
    }
    __shared__ float2 sh[8];
    __shared__ float sga[16], sbe[16];
    if ((threadIdx.x & 31) == 0) sh[threadIdx.x >> 5] = make_float2(s, s2);
    __syncthreads();
    if (threadIdx.x < 16) {
        float ts = 0.f, ts2 = 0.f;
        #pragma unroll
        for (int i = 0; i < 8; i++) { ts += sh[i].x; ts2 += sh[i].y; }
        const float inv = 1.f / (float)(CG * NN_);
        float mu  = ts * inv;
        float var = ts2 * inv - mu * mu;
        float rstd = rsqrtf(var + 1e-5f);
        int c = g * CG + threadIdx.x;
        float ga = gamma[c] * rstd;
        sga[threadIdx.x] = ga;
        sbe[threadIdx.x] = beta[c] - mu * ga;
    }
    __syncthreads();

    for (int n = threadIdx.x; n < NN_; n += 256) {
        __align__(16) __half hh[16];
        #pragma unroll
        for (int c = 0; c < 16; c++)
            hh[c] = __float2half_rn(xs[c * NN_ + n] * sga[c] + sbe[c]);
        size_t o = ((size_t)(b * NN_ + n)) * CC + g * CG;
        *(uint4*)(g_xn + o)     = *(uint4*)(hh);
        *(uint4*)(g_xn + o + 8) = *(uint4*)(hh + 8);
    }
}

// ---------------------------------------------------------------------------
// fp16 HMMA GEMM:  D[M,N] = sum_k A[m][k] * B[n][k]   (both K-major)
// 128x128 CTA tile, BK=64, 8 warps (64x32), 3-stage cp.async ring, 2 CTA/SM.
// B fragments via 16-row ldsm4 (2 per k16 instead of 4 ldsm2).
// EPI: 0=fp16+col bias, 1=fp16+row bias, 2=fp16*SCALE, 3=fp16, 4=fp32+row bias+resid
// ---------------------------------------------------------------------------
#define STAGE_BYTES 32768              // A 16KB + B 16KB
#define NSTAGE      3
#define SMEM_BYTES  (NSTAGE * STAGE_BYTES)

template<int EPI>
__global__ void __launch_bounds__(256, 2) gemm_hh(
    const __half* __restrict__ A, size_t aBatch, int ldA,
    const __half* __restrict__ B, size_t bBatch, int ldB,
    int K,
    __half* __restrict__ outH, float* __restrict__ outF,
    size_t oBatch, int ldO,
    const float* __restrict__ bias, const float* __restrict__ resid)
{
    extern __shared__ char smem[];
    const uint32_t sb = smem_u32(smem);

    const int tid = threadIdx.x, lane = tid & 31, wid = tid >> 5;
    const int wm = wid >> 2, wn = wid & 3;
    const int b  = blockIdx.z;
    const int m0 = blockIdx.y * 128, n0 = blockIdx.x * 128;

    const __half* srcA = A + (size_t)b * aBatch + (size_t)m0 * ldA;
    const __half* srcB = B + (size_t)b * bBatch + (size_t)n0 * ldB;

    float acc[4][4][4];
    #pragma unroll
    for (int i = 0; i < 4; i++)
        #pragma unroll
        for (int j = 0; j < 4; j++)
            #pragma unroll
            for (int q = 0; q < 4; q++) acc[i][j][q] = 0.f;

    const int T = K / 64;

    const int l_row = tid >> 1;
    const int l_g0  = (tid & 1) * 4;
    auto load_stage = [&](int t) {
        const int k0 = t * 64;
        const uint32_t sbuf = sb + (uint32_t)(t % NSTAGE) * STAGE_BYTES;
        const uint32_t rowOff = (uint32_t)l_row * 128;
        #pragma unroll
        for (int q = 0; q < 4; q++) {
            const int g = l_g0 + q;
            const uint32_t sw = (uint32_t)((g ^ (l_row & 7)) << 4);
            cp16(sbuf + rowOff + sw,          srcA + (size_t)l_row * ldA + k0 + g * 8);
            cp16(sbuf + 16384 + rowOff + sw,  srcB + (size_t)l_row * ldB + k0 + g * 8);
        }
    };

    const int arow = lane & 15;
    const int akhi = lane >> 4;
    const int brow = ((lane >> 4) << 3) | (lane & 7);  // 16-row ldsm4 pattern
    const int bkhi = (lane >> 3) & 1;
    const uint32_t aRowOff = (uint32_t)(wm * 64 + arow) * 128;
    const uint32_t bRowOff = (uint32_t)(wn * 32 + brow) * 128 + 16384u;
    const uint32_t l7 = (uint32_t)(lane & 7);

    load_stage(0); cp_commit();
    load_stage(1); cp_commit();

    for (int t = 0; t < T; t++) {
        cp_wait<1>();
        __syncthreads();
        if (t + 2 < T) load_stage(t + 2);
        cp_commit();

        const uint32_t sbuf = sb + (uint32_t)(t % NSTAGE) * STAGE_BYTES;
        #pragma unroll
        for (int k16 = 0; k16 < 4; k16++) {
            const uint32_t aSw = (uint32_t)(((k16 * 2 + akhi) ^ (arow & 7)) << 4);
            const uint32_t bSw = (uint32_t)(((k16 * 2 + bkhi) ^ l7) << 4);
            uint32_t af[4][4], bf[2][4];
            #pragma unroll
            for (int i = 0; i < 4; i++)
                ldsm4(af[i], sbuf + aRowOff + (uint32_t)(i * 16 * 128) + aSw);
            #pragma unroll
            for (int j = 0; j < 2; j++)
                ldsm4(bf[j], sbuf + bRowOff + (uint32_t)(j * 16 * 128) + bSw);
            #pragma unroll
            for (int i = 0; i < 4; i++)
                #pragma unroll
                for (int j = 0; j < 2; j++) {
                    mma16816(acc[i][2 * j],     af[i], bf[j][0], bf[j][1]);
                    mma16816(acc[i][2 * j + 1], af[i], bf[j][2], bf[j][3]);
                }
        }
    }

    // epilogue
    const int rbase = m0 + wm * 64 + (lane >> 2);
    const int cbase = n0 + wn * 32 + (lane & 3) * 2;

    float bc0[4], bc1[4];
    if (EPI == 0) {
        #pragma unroll
        for (int j = 0; j < 4; j++) { bc0[j] = bias[cbase + j * 8]; bc1[j] = bias[cbase + j * 8 + 1]; }
    }

    #pragma unroll
    for (int i = 0; i < 4; i++) {
        const int row0 = rbase + i * 16, row1 = row0 + 8;
        float br0 = 0.f, br1 = 0.f;
        if (EPI == 1 || EPI == 4) { br0 = bias[row0]; br1 = bias[row1]; }
        #pragma unroll
        for (int j = 0; j < 4; j++) {
            const int col = cbase + j * 8;
            const size_t ob0 = (size_t)b * oBatch + (size_t)row0 * ldO + col;
            const size_t ob1 = (size_t)b * oBatch + (size_t)row1 * ldO + col;
            float v0 = acc[i][j][0], v1 = acc[i][j][1];
            float v2 = acc[i][j][2], v3 = acc[i][j][3];
            if (EPI == 2) {
                *(__half2*)(outH + ob0) = __floats2half2_rn(v0 * SCALE, v1 * SCALE);
                *(__half2*)(outH + ob1) = __floats2half2_rn(v2 * SCALE, v3 * SCALE);
            } else if (EPI == 4) {
                float2 r0 = *(const float2*)(resid + ob0);
                float2 r1 = *(const float2*)(resid + ob1);
                *(float2*)(outF + ob0) = make_float2(v0 + br0 + r0.x, v1 + br0 + r0.y);
                *(float2*)(outF + ob1) = make_float2(v2 + br1 + r1.x, v3 + br1 + r1.y);
            } else {
                if (EPI == 0) { v0 += bc0[j]; v1 += bc1[j]; v2 += bc0[j]; v3 += bc1[j]; }
                if (EPI == 1) { v0 += br0;    v1 += br0;    v2 += br1;    v3 += br1;   }
                *(__half2*)(outH + ob0) = __floats2half2_rn(v0, v1);
                *(__half2*)(outH + ob1) = __floats2half2_rn(v2, v3);
            }
        }
    }
}

// ---------------------------------------------------------------------------
// Softmax over rows of fp16 scores -> fp16 attn. 256 thr, 4 halves/thread.
// ---------------------------------------------------------------------------
__global__ void softmax_kernel(const __half* __restrict__ src, __half* __restrict__ dst) {
    const size_t rbase = (size_t)blockIdx.x * NN_;
    uint2 rv = *(const uint2*)(src + rbase + threadIdx.x * 4);
    float2 a0 = __half22float2(*(const __half2*)&rv.x);
    float2 a1 = __half22float2(*(const __half2*)&rv.y);

    float m = fmaxf(fmaxf(a0.x, a0.y), fmaxf(a1.x, a1.y));
    #pragma unroll
    for (int o = 16; o; o >>= 1) m = fmaxf(m, __shfl_xor_sync(0xffffffffu, m, o));
    __shared__ float shm[8], shs[8];
    if ((threadIdx.x & 31) == 0) shm[threadIdx.x >> 5] = m;
    __syncthreads();
    float M = shm[0];
    #pragma unroll
    for (int i = 1; i < 8; i++) M = fmaxf(M, shm[i]);

    a0.x = __expf(a0.x - M); a0.y = __expf(a0.y - M);
    a1.x = __expf(a1.x - M); a1.y = __expf(a1.y - M);
    float s = a0.x + a0.y + a1.x + a1.y;
    #pragma unroll
    for (int o = 16; o; o >>= 1) s += __shfl_xor_sync(0xffffffffu, s, o);
    if ((threadIdx.x & 31) == 0) shs[threadIdx.x >> 5] = s;
    __syncthreads();
    float S = 0.f;
    #pragma unroll
    for (int i = 0; i < 8; i++) S += shs[i];
    const float r = 1.f / S;

    __half2 h0 = __floats2half2_rn(a0.x * r, a0.y * r);
    __half2 h1 = __floats2half2_rn(a1.x * r, a1.y * r);
    uint2 wv;
    wv.x = *(const uint32_t*)&h0;
    wv.y = *(const uint32_t*)&h1;
    *(uint2*)(dst + rbase + threadIdx.x * 4) = wv;
}

// ---------------------------------------------------------------------------
// Launch — dual 8-batch chains on two streams + V/cvt on a third.
// ---------------------------------------------------------------------------
static cudaStream_t sB = nullptr, sV = nullptr;
static cudaEvent_t evFork = nullptr, evGN = nullptr, evCvt = nullptr,
                   evV = nullptr, evP1 = nullptr;

extern "C" void kernel_launch(void* const* d_in, const int* in_sizes, int n_in,
                              void* d_out, int out_size) {
    const float* x      = (const float*)d_in[0];
    const float* gamma  = (const float*)d_in[1];
    const float* beta   = (const float*)d_in[2];
    const float* w_qkv  = (const float*)d_in[3];
    const float* b_qkv  = (const float*)d_in[4];
    const float* w_proj = (const float*)d_in[5];
    const float* b_proj = (const float*)d_in[6];
    float* y = (float*)d_out;

    if (!sB) {
        cudaStreamCreateWithFlags(&sB, cudaStreamNonBlocking);
        cudaStreamCreateWithFlags(&sV, cudaStreamNonBlocking);
        cudaEventCreateWithFlags(&evFork, cudaEventDisableTiming);
        cudaEventCreateWithFlags(&evGN,   cudaEventDisableTiming);
        cudaEventCreateWithFlags(&evCvt,  cudaEventDisableTiming);
        cudaEventCreateWithFlags(&evV,    cudaEventDisableTiming);
        cudaEventCreateWithFlags(&evP1,   cudaEventDisableTiming);
    }

    cudaFuncSetAttribute(gn_kernel,  cudaFuncAttributeMaxDynamicSharedMemorySize, 65536);
    cudaFuncSetAttribute(gemm_hh<0>, cudaFuncAttributeMaxDynamicSharedMemorySize, SMEM_BYTES);
    cudaFuncSetAttribute(gemm_hh<1>, cudaFuncAttributeMaxDynamicSharedMemorySize, SMEM_BYTES);
    cudaFuncSetAttribute(gemm_hh<2>, cudaFuncAttributeMaxDynamicSharedMemorySize, SMEM_BYTES);
    cudaFuncSetAttribute(gemm_hh<3>, cudaFuncAttributeMaxDynamicSharedMemorySize, SMEM_BYTES);
    cudaFuncSetAttribute(gemm_hh<4>, cudaFuncAttributeMaxDynamicSharedMemorySize, SMEM_BYTES);

    __half *xn, *wq, *wp, *qkt, *v, *s16, *a, *av;
    cudaGetSymbolAddress((void**)&xn,  g_xn);
    cudaGetSymbolAddress((void**)&wq,  g_wq);
    cudaGetSymbolAddress((void**)&wp,  g_wp);
    cudaGetSymbolAddress((void**)&qkt, g_qkt);
    cudaGetSymbolAddress((void**)&v,   g_v);
    cudaGetSymbolAddress((void**)&s16, g_s);
    cudaGetSymbolAddress((void**)&a,   g_a);
    cudaGetSymbolAddress((void**)&av,  g_av);

    const int HB = BB / 2;                           // 8 batches per chain
    const size_t bQ = (size_t)NN_ * NN_;             // qkt/s/a batch stride
    const size_t bX = (size_t)NN_ * CC;              // xn/av batch stride
    const size_t bV = (size_t)CC * NN_;              // v / y / x batch stride

    // fork: sV handles converts (independent of GN)
    cudaEventRecord(evFork, 0);
    cudaStreamWaitEvent(sV, evFork, 0);
    cudaStreamWaitEvent(sB, evFork, 0);

    cvt_kernel<<<(3 * CC * CC + 255) / 256, 256, 0, sV>>>(w_qkv, wq, 3 * CC * CC);
    cvt_kernel<<<(CC * CC + 255) / 256, 256, 0, sV>>>(w_proj, wp, CC * CC);
    cudaEventRecord(evCvt, sV);

    // main: GroupNorm (all batches)
    gn_kernel<<<BB * 32, 256, 65536>>>(x, gamma, beta);
    cudaEventRecord(evGN, 0);

    // sV: V GEMM over all 16 batches (cvt already ordered on sV)
    cudaStreamWaitEvent(sV, evGN, 0);
    gemm_hh<1><<<dim3(8, 4, BB), 256, SMEM_BYTES, sV>>>(
        wq + (size_t)2 * CC * CC, 0, CC,
        xn, bX, CC, CC,
        v, nullptr, bV, NN_, b_qkv + 2 * CC, nullptr);
    cudaEventRecord(evV, sV);

    // ---- chain 0 (batches 0-7) on stream 0; chain 1 (batches 8-15) on sB ----
    cudaStreamWaitEvent(0, evCvt, 0);
    cudaStreamWaitEvent(sB, evCvt, 0);
    cudaStreamWaitEvent(sB, evGN, 0);

    for (int h = 0; h < 2; h++) {
        cudaStream_t st = h ? sB : 0;
        const int bo = h * HB;
        __half* qkt_h = qkt + (size_t)bo * bQ;
        __half* s_h   = s16 + (size_t)bo * bQ;
        __half* a_h   = a   + (size_t)bo * bQ;
        __half* xn_h  = xn  + (size_t)bo * bX;
        __half* v_h   = v   + (size_t)bo * bV;
        __half* av_h  = av  + (size_t)bo * bX;
        float*  y_h   = y   + (size_t)bo * bV;
        const float* x_h = x + (size_t)bo * bV;

        // QK
        gemm_hh<0><<<dim3(8, 8, HB), 256, SMEM_BYTES, st>>>(
            xn_h, bX, CC,
            wq, 0, CC, CC,
            qkt_h, nullptr, bQ, NN_, b_qkv, nullptr);

        // scores (fp16, scaled)
        gemm_hh<2><<<dim3(8, 8, HB), 256, SMEM_BYTES, st>>>(
            qkt_h, bQ, NN_,
            qkt_h + CC, bQ, NN_, CC,
            s_h, nullptr, bQ, NN_, nullptr, nullptr);

        softmax_kernel<<<HB * NN_, 256, 0, st>>>(s_h, a_h);

        // AV needs g_v
        cudaStreamWaitEvent(st, evV, 0);
        gemm_hh<3><<<dim3(4, 8, HB), 256, SMEM_BYTES, st>>>(
            a_h, bQ, NN_,
            v_h, bV, NN_, NN_,
            av_h, nullptr, bX, CC, nullptr, nullptr);

        // proj + residual
        gemm_hh<4><<<dim3(8, 4, HB), 256, SMEM_BYTES, st>>>(
            wp, 0, CC,
            av_h, bX, CC, CC,
            nullptr, y_h, bV, NN_, b_proj, x_h);
    }

    // join chain 1 back into stream 0
    cudaEventRecord(evP1, sB);
    cudaStreamWaitEvent(0, evP1, 0);
}

// round 11
// speedup vs baseline: 1.2276x; 1.0445x over previous
#include <cuda_runtime.h>
#include <cuda_fp16.h>
#include <math.h>
#include <stdint.h>

// Problem constants: B=16, C=512, H=W=32, GROUPS=32
#define BB   16
#define CC   512
#define NN_  1024
#define CG   16
#define SCALE 0.044194173824159216f   // 512^-0.5

// ---------------------------------------------------------------------------
// Scratch (device globals)
// ---------------------------------------------------------------------------
__device__ __align__(128) __half g_xn [(size_t)BB * NN_ * CC];   // xn_t [b][n][c]
__device__ __align__(128) __half g_wq [(size_t)3 * CC * CC];     // w_qkv fp16
__device__ __align__(128) __half g_wp [(size_t)CC * CC];         // w_proj fp16
__device__ __align__(128) __half g_qkt[(size_t)BB * NN_ * NN_];  // [b][n][o] (q|k)
__device__ __align__(128) __half g_v  [(size_t)BB * CC * NN_];   // v [b][c][n]
__device__ __align__(128) __half g_s  [(size_t)BB * NN_ * NN_];  // scaled scores fp16
__device__ __align__(128) __half g_a  [(size_t)BB * NN_ * NN_];  // attn fp16
__device__ __align__(128) __half g_av [(size_t)BB * NN_ * CC];   // av_t [b][n][c]

// ---------------------------------------------------------------------------
// Helpers (base-target sm_80+ only)
// ---------------------------------------------------------------------------
__device__ __forceinline__ uint32_t smem_u32(const void* p) {
    uint32_t a;
    asm("{ .reg .u64 t; cvta.to.shared.u64 t, %1; cvt.u32.u64 %0, t; }" : "=r"(a) : "l"(p));
    return a;
}
__device__ __forceinline__ void ldsm4(uint32_t (&r)[4], uint32_t addr) {
    asm volatile("ldmatrix.sync.aligned.m8n8.x4.shared.b16 {%0,%1,%2,%3}, [%4];"
        : "=r"(r[0]), "=r"(r[1]), "=r"(r[2]), "=r"(r[3]) : "r"(addr));
}
__device__ __forceinline__ void mma16816(float (&c)[4], const uint32_t (&a)[4],
                                         const uint32_t b0, const uint32_t b1) {
    asm volatile("mma.sync.aligned.m16n8k16.row.col.f32.f16.f16.f32 "
        "{%0,%1,%2,%3}, {%4,%5,%6,%7}, {%8,%9}, {%0,%1,%2,%3};"
        : "+f"(c[0]), "+f"(c[1]), "+f"(c[2]), "+f"(c[3])
        : "r"(a[0]), "r"(a[1]), "r"(a[2]), "r"(a[3]), "r"(b0), "r"(b1));
}
__device__ __forceinline__ void cp16(uint32_t dst, const void* src) {
    asm volatile("cp.async.cg.shared.global [%0], [%1], 16;" :: "r"(dst), "l"(src));
}
__device__ __forceinline__ void cp_commit() {
    asm volatile("cp.async.commit_group;" ::: "memory");
}
template<int N> __device__ __forceinline__ void cp_wait() {
    asm volatile("cp.async.wait_group %0;" :: "n"(N) : "memory");
}

// ---------------------------------------------------------------------------
// fp32 -> fp16 convert
// ---------------------------------------------------------------------------
__global__ void cvt_kernel(const float* __restrict__ src, __half* __restrict__ dst, int n) {
    int i = blockIdx.x * blockDim.x + threadIdx.x;
    if (i < n) dst[i] = __float2half_rn(src[i]);
}

// ---------------------------------------------------------------------------
// GroupNorm -> transposed fp16 output xn_t[b][n][c]
// ---------------------------------------------------------------------------
__global__ void gn_kernel(const float* __restrict__ x,
                          const float* __restrict__ gamma,
                          const float* __restrict__ beta) {
    extern __shared__ float xs[];              // 16 ch x 1024 px
    const int b = blockIdx.x >> 5;
    const int g = blockIdx.x & 31;
    const size_t base = ((size_t)b * CC + (size_t)g * CG) * NN_;
    const float4* __restrict__ x4 = (const float4*)(x + base);

    float s = 0.f, s2 = 0.f;
    for (int i = threadIdx.x; i < CG * NN_ / 4; i += 256) {
        float4 v = x4[i];
        ((float4*)xs)[i] = v;
        s  += v.x + v.y + v.z + v.w;
        s2 += v.x * v.x + v.y * v.y + v.z * v.z + v.w * v.w;
    }
    #pragma unroll
    for (int o = 16; o; o >>= 1) {
        s  += __shfl_down_sync(0xffffffffu, s,  o);
        s2 += __shfl_down_sync(0xffffffffu, s2, o);
    }
    __shared__ float2 sh[8];
    __shared__ float sga[16], sbe[16];
    if ((threadIdx.x & 31) == 0) sh[threadIdx.x >> 5] = make_float2(s, s2);
    __syncthreads();
    if (threadIdx.x < 16) {
        float ts = 0.f, ts2 = 0.f;
        #pragma unroll
        for (int i = 0; i < 8; i++) { ts += sh[i].x; ts2 += sh[i].y; }
        const float inv = 1.f / (float)(CG * NN_);
        float mu  = ts * inv;
        float var = ts2 * inv - mu * mu;
        float rstd = rsqrtf(var + 1e-5f);
        int c = g * CG + threadIdx.x;
        float ga = gamma[c] * rstd;
        sga[threadIdx.x] = ga;
        sbe[threadIdx.x] = beta[c] - mu * ga;
    }
    __syncthreads();

    for (int n = threadIdx.x; n < NN_; n += 256) {
        __align__(16) __half hh[16];
        #pragma unroll
        for (int c = 0; c < 16; c++)
            hh[c] = __float2half_rn(xs[c * NN_ + n] * sga[c] + sbe[c]);
        size_t o = ((size_t)(b * NN_ + n)) * CC + g * CG;
        *(uint4*)(g_xn + o)     = *(uint4*)(hh);
        *(uint4*)(g_xn + o + 8) = *(uint4*)(hh + 8);
    }
}

// ---------------------------------------------------------------------------
// fp16 HMMA GEMM:  D[M,N] = sum_k A[m][k] * B[n][k]   (both K-major)
// 128x128 CTA tile, BK=64, 8 warps (64x32), 3-stage cp.async ring, 2 CTA/SM.
// Register-level fragment double-buffering across k16 steps.
// EPI: 0=fp16+col bias, 1=fp16+row bias, 2=fp16*SCALE, 3=fp16, 4=fp32+row bias+resid
// ---------------------------------------------------------------------------
#define STAGE_BYTES 32768              // A 16KB + B 16KB
#define NSTAGE      3
#define SMEM_BYTES  (NSTAGE * STAGE_BYTES)

template<int EPI>
__global__ void __launch_bounds__(256, 2) gemm_hh(
    const __half* __restrict__ A, size_t aBatch, int ldA,
    const __half* __restrict__ B, size_t bBatch, int ldB,
    int K,
    __half* __restrict__ outH, float* __restrict__ outF,
    size_t oBatch, int ldO,
    const float* __restrict__ bias, const float* __restrict__ resid)
{
    extern __shared__ char smem[];
    const uint32_t sb = smem_u32(smem);

    const int tid = threadIdx.x, lane = tid & 31, wid = tid >> 5;
    const int wm = wid >> 2, wn = wid & 3;
    const int b  = blockIdx.z;
    const int m0 = blockIdx.y * 128, n0 = blockIdx.x * 128;

    const __half* srcA = A + (size_t)b * aBatch + (size_t)m0 * ldA;
    const __half* srcB = B + (size_t)b * bBatch + (size_t)n0 * ldB;

    float acc[4][4][4];
    #pragma unroll
    for (int i = 0; i < 4; i++)
        #pragma unroll
        for (int j = 0; j < 4; j++)
            #pragma unroll
            for (int q = 0; q < 4; q++) acc[i][j][q] = 0.f;

    const int T = K / 64;

    const int l_row = tid >> 1;
    const int l_g0  = (tid & 1) * 4;
    auto load_stage = [&](int t) {
        const int k0 = t * 64;
        const uint32_t sbuf = sb + (uint32_t)(t % NSTAGE) * STAGE_BYTES;
        const uint32_t rowOff = (uint32_t)l_row * 128;
        #pragma unroll
        for (int q = 0; q < 4; q++) {
            const int g = l_g0 + q;
            const uint32_t sw = (uint32_t)((g ^ (l_row & 7)) << 4);
            cp16(sbuf + rowOff + sw,          srcA + (size_t)l_row * ldA + k0 + g * 8);
            cp16(sbuf + 16384 + rowOff + sw,  srcB + (size_t)l_row * ldB + k0 + g * 8);
        }
    };

    const int arow = lane & 15;
    const int akhi = lane >> 4;
    const int brow = ((lane >> 4) << 3) | (lane & 7);  // 16-row ldsm4 pattern
    const int bkhi = (lane >> 3) & 1;
    const uint32_t aRowOff = (uint32_t)(wm * 64 + arow) * 128;
    const uint32_t bRowOff = (uint32_t)(wn * 32 + brow) * 128 + 16384u;
    const uint32_t l7 = (uint32_t)(lane & 7);

    // double-buffered register fragments
    uint32_t af[2][4][4], bf[2][2][4];

    auto ld_frags = [&](uint32_t sbuf, int k16, int buf) {
        const uint32_t aSw = (uint32_t)(((k16 * 2 + akhi) ^ l7) << 4);
        const uint32_t bSw = (uint32_t)(((k16 * 2 + bkhi) ^ l7) << 4);
        #pragma unroll
        for (int i = 0; i < 4; i++)
            ldsm4(af[buf][i], sbuf + aRowOff + (uint32_t)(i * 16 * 128) + aSw);
        #pragma unroll
        for (int j = 0; j < 2; j++)
            ldsm4(bf[buf][j], sbuf + bRowOff + (uint32_t)(j * 16 * 128) + bSw);
    };

    load_stage(0); cp_commit();
    load_stage(1); cp_commit();

    for (int t = 0; t < T; t++) {
        cp_wait<1>();
        __syncthreads();

        const uint32_t sbuf = sb + (uint32_t)(t % NSTAGE) * STAGE_BYTES;
        ld_frags(sbuf, 0, 0);              // prefetch k16=0 before issuing next cp.async

        if (t + 2 < T) load_stage(t + 2);
        cp_commit();

        #pragma unroll
        for (int k16 = 0; k16 < 4; k16++) {
            const int cur = k16 & 1;
            if (k16 < 3) ld_frags(sbuf, k16 + 1, cur ^ 1);   // hide LDS under mma
            #pragma unroll
            for (int i = 0; i < 4; i++)
                #pragma unroll
                for (int j = 0; j < 2; j++) {
                    mma16816(acc[i][2 * j],     af[cur][i], bf[cur][j][0], bf[cur][j][1]);
                    mma16816(acc[i][2 * j + 1], af[cur][i], bf[cur][j][2], bf[cur][j][3]);
                }
        }
    }

    // epilogue
    const int rbase = m0 + wm * 64 + (lane >> 2);
    const int cbase = n0 + wn * 32 + (lane & 3) * 2;

    float bc0[4], bc1[4];
    if (EPI == 0) {
        #pragma unroll
        for (int j = 0; j < 4; j++) { bc0[j] = bias[cbase + j * 8]; bc1[j] = bias[cbase + j * 8 + 1]; }
    }

    #pragma unroll
    for (int i = 0; i < 4; i++) {
        const int row0 = rbase + i * 16, row1 = row0 + 8;
        float br0 = 0.f, br1 = 0.f;
        if (EPI == 1 || EPI == 4) { br0 = bias[row0]; br1 = bias[row1]; }
        #pragma unroll
        for (int j = 0; j < 4; j++) {
            const int col = cbase + j * 8;
            const size_t ob0 = (size_t)b * oBatch + (size_t)row0 * ldO + col;
            const size_t ob1 = (size_t)b * oBatch + (size_t)row1 * ldO + col;
            float v0 = acc[i][j][0], v1 = acc[i][j][1];
            float v2 = acc[i][j][2], v3 = acc[i][j][3];
            if (EPI == 2) {
                *(__half2*)(outH + ob0) = __floats2half2_rn(v0 * SCALE, v1 * SCALE);
                *(__half2*)(outH + ob1) = __floats2half2_rn(v2 * SCALE, v3 * SCALE);
            } else if (EPI == 4) {
                float2 r0 = *(const float2*)(resid + ob0);
                float2 r1 = *(const float2*)(resid + ob1);
                *(float2*)(outF + ob0) = make_float2(v0 + br0 + r0.x, v1 + br0 + r0.y);
                *(float2*)(outF + ob1) = make_float2(v2 + br1 + r1.x, v3 + br1 + r1.y);
            } else {
                if (EPI == 0) { v0 += bc0[j]; v1 += bc1[j]; v2 += bc0[j]; v3 += bc1[j]; }
                if (EPI == 1) { v0 += br0;    v1 += br0;    v2 += br1;    v3 += br1;   }
                *(__half2*)(outH + ob0) = __floats2half2_rn(v0, v1);
                *(__half2*)(outH + ob1) = __floats2half2_rn(v2, v3);
            }
        }
    }
}

// ---------------------------------------------------------------------------
// Softmax over rows of fp16 scores -> fp16 attn. 256 thr, 4 halves/thread.
// ---------------------------------------------------------------------------
__global__ void softmax_kernel(const __half* __restrict__ src, __half* __restrict__ dst) {
    const size_t rbase = (size_t)blockIdx.x * NN_;
    uint2 rv = *(const uint2*)(src + rbase + threadIdx.x * 4);
    float2 a0 = __half22float2(*(const __half2*)&rv.x);
    float2 a1 = __half22float2(*(const __half2*)&rv.y);

    float m = fmaxf(fmaxf(a0.x, a0.y), fmaxf(a1.x, a1.y));
    #pragma unroll
    for (int o = 16; o; o >>= 1) m = fmaxf(m, __shfl_xor_sync(0xffffffffu, m, o));
    __shared__ float shm[8], shs[8];
    if ((threadIdx.x & 31) == 0) shm[threadIdx.x >> 5] = m;
    __syncthreads();
    float M = shm[0];
    #pragma unroll
    for (int i = 1; i < 8; i++) M = fmaxf(M, shm[i]);

    a0.x = __expf(a0.x - M); a0.y = __expf(a0.y - M);
    a1.x = __expf(a1.x - M); a1.y = __expf(a1.y - M);
    float s = a0.x + a0.y + a1.x + a1.y;
    #pragma unroll
    for (int o = 16; o; o >>= 1) s += __shfl_xor_sync(0xffffffffu, s, o);
    if ((threadIdx.x & 31) == 0) shs[threadIdx.x >> 5] = s;
    __syncthreads();
    float S = 0.f;
    #pragma unroll
    for (int i = 0; i < 8; i++) S += shs[i];
    const float r = 1.f / S;

    __half2 h0 = __floats2half2_rn(a0.x * r, a0.y * r);
    __half2 h1 = __floats2half2_rn(a1.x * r, a1.y * r);
    uint2 wv;
    wv.x = *(const uint32_t*)&h0;
    wv.y = *(const uint32_t*)&h1;
    *(uint2*)(dst + rbase + threadIdx.x * 4) = wv;
}

// ---------------------------------------------------------------------------
// Launch — dual 8-batch chains on two streams + V/cvt on a third.
// ---------------------------------------------------------------------------
static cudaStream_t sB = nullptr, sV = nullptr;
static cudaEvent_t evFork = nullptr, evGN = nullptr, evCvt = nullptr,
                   evV = nullptr, evP1 = nullptr;

extern "C" void kernel_launch(void* const* d_in, const int* in_sizes, int n_in,
                              void* d_out, int out_size) {
    const float* x      = (const float*)d_in[0];
    const float* gamma  = (const float*)d_in[1];
    const float* beta   = (const float*)d_in[2];
    const float* w_qkv  = (const float*)d_in[3];
    const float* b_qkv  = (const float*)d_in[4];
    const float* w_proj = (const float*)d_in[5];
    const float* b_proj = (const float*)d_in[6];
    float* y = (float*)d_out;

    if (!sB) {
        cudaStreamCreateWithFlags(&sB, cudaStreamNonBlocking);
        cudaStreamCreateWithFlags(&sV, cudaStreamNonBlocking);
        cudaEventCreateWithFlags(&evFork, cudaEventDisableTiming);
        cudaEventCreateWithFlags(&evGN,   cudaEventDisableTiming);
        cudaEventCreateWithFlags(&evCvt,  cudaEventDisableTiming);
        cudaEventCreateWithFlags(&evV,    cudaEventDisableTiming);
        cudaEventCreateWithFlags(&evP1,   cudaEventDisableTiming);
    }

    cudaFuncSetAttribute(gn_kernel,  cudaFuncAttributeMaxDynamicSharedMemorySize, 65536);
    cudaFuncSetAttribute(gemm_hh<0>, cudaFuncAttributeMaxDynamicSharedMemorySize, SMEM_BYTES);
    cudaFuncSetAttribute(gemm_hh<1>, cudaFuncAttributeMaxDynamicSharedMemorySize, SMEM_BYTES);
    cudaFuncSetAttribute(gemm_hh<2>, cudaFuncAttributeMaxDynamicSharedMemorySize, SMEM_BYTES);
    cudaFuncSetAttribute(gemm_hh<3>, cudaFuncAttributeMaxDynamicSharedMemorySize, SMEM_BYTES);
    cudaFuncSetAttribute(gemm_hh<4>, cudaFuncAttributeMaxDynamicSharedMemorySize, SMEM_BYTES);

    __half *xn, *wq, *wp, *qkt, *v, *s16, *a, *av;
    cudaGetSymbolAddress((void**)&xn,  g_xn);
    cudaGetSymbolAddress((void**)&wq,  g_wq);
    cudaGetSymbolAddress((void**)&wp,  g_wp);
    cudaGetSymbolAddress((void**)&qkt, g_qkt);
    cudaGetSymbolAddress((void**)&v,   g_v);
    cudaGetSymbolAddress((void**)&s16, g_s);
    cudaGetSymbolAddress((void**)&a,   g_a);
    cudaGetSymbolAddress((void**)&av,  g_av);

    const int HB = BB / 2;                           // 8 batches per chain
    const size_t bQ = (size_t)NN_ * NN_;             // qkt/s/a batch stride
    const size_t bX = (size_t)NN_ * CC;              // xn/av batch stride
    const size_t bV = (size_t)CC * NN_;              // v / y / x batch stride

    // fork: sV handles converts (independent of GN)
    cudaEventRecord(evFork, 0);
    cudaStreamWaitEvent(sV, evFork, 0);
    cudaStreamWaitEvent(sB, evFork, 0);

    cvt_kernel<<<(3 * CC * CC + 255) / 256, 256, 0, sV>>>(w_qkv, wq, 3 * CC * CC);
    cvt_kernel<<<(CC * CC + 255) / 256, 256, 0, sV>>>(w_proj, wp, CC * CC);
    cudaEventRecord(evCvt, sV);

    // main: GroupNorm (all batches)
    gn_kernel<<<BB * 32, 256, 65536>>>(x, gamma, beta);
    cudaEventRecord(evGN, 0);

    // sV: V GEMM over all 16 batches (cvt already ordered on sV)
    cudaStreamWaitEvent(sV, evGN, 0);
    gemm_hh<1><<<dim3(8, 4, BB), 256, SMEM_BYTES, sV>>>(
        wq + (size_t)2 * CC * CC, 0, CC,
        xn, bX, CC, CC,
        v, nullptr, bV, NN_, b_qkv + 2 * CC, nullptr);
    cudaEventRecord(evV, sV);

    // ---- chain 0 (batches 0-7) on stream 0; chain 1 (batches 8-15) on sB ----
    cudaStreamWaitEvent(0, evCvt, 0);
    cudaStreamWaitEvent(sB, evCvt, 0);
    cudaStreamWaitEvent(sB, evGN, 0);

    for (int h = 0; h < 2; h++) {
        cudaStream_t st = h ? sB : 0;
        const int bo = h * HB;
        __half* qkt_h = qkt + (size_t)bo * bQ;
        __half* s_h   = s16 + (size_t)bo * bQ;
        __half* a_h   = a   + (size_t)bo * bQ;
        __half* xn_h  = xn  + (size_t)bo * bX;
        __half* v_h   = v   + (size_t)bo * bV;
        __half* av_h  = av  + (size_t)bo * bX;
        float*  y_h   = y   + (size_t)bo * bV;
        const float* x_h = x + (size_t)bo * bV;

        // QK
        gemm_hh<0><<<dim3(8, 8, HB), 256, SMEM_BYTES, st>>>(
            xn_h, bX, CC,
            wq, 0, CC, CC,
            qkt_h, nullptr, bQ, NN_, b_qkv, nullptr);

        // scores (fp16, scaled)
        gemm_hh<2><<<dim3(8, 8, HB), 256, SMEM_BYTES, st>>>(
            qkt_h, bQ, NN_,
            qkt_h + CC, bQ, NN_, CC,
            s_h, nullptr, bQ, NN_, nullptr, nullptr);

        softmax_kernel<<<HB * NN_, 256, 0, st>>>(s_h, a_h);

        // AV needs g_v
        cudaStreamWaitEvent(st, evV, 0);
        gemm_hh<3><<<dim3(4, 8, HB), 256, SMEM_BYTES, st>>>(
            a_h, bQ, NN_,
            v_h, bV, NN_, NN_,
            av_h, nullptr, bX, CC, nullptr, nullptr);

        // proj + residual
        gemm_hh<4><<<dim3(8, 4, HB), 256, SMEM_BYTES, st>>>(
            wp, 0, CC,
            av_h, bX, CC, CC,
            nullptr, y_h, bV, NN_, b_proj, x_h);
    }

    // join chain 1 back into stream 0
    cudaEventRecord(evP1, sB);
    cudaStreamWaitEvent(0, evP1, 0);
}